// round 1
// baseline (speedup 1.0000x reference)
#include <cuda_runtime.h>
#include <math_constants.h>

// Problem constants (fixed by setup_inputs)
#define BB 2
#define SS 2048
#define HH 16
#define DKK 64
#define DD 1024
#define MM (BB*SS)   // 4096

// Scratch (allocation-free rule: __device__ globals)
__device__ float g_q[(size_t)MM * DD];
__device__ float g_k[(size_t)MM * DD];
__device__ float g_v[(size_t)MM * DD];
__device__ float g_attn[(size_t)MM * DD];

// ---------------------------------------------------------------------------
// SGEMM: C[M,N] = A[M,K] @ W[N,K]^T + bias   (both A and W are K-contiguous)
// mode 0: write out[m*N + n] (plain row-major, used for final projection)
// mode 1: write [b,h,s,dk] layout (V projection)
// mode 2: write [b,h,s,dk] layout with RoPE applied (Q,K projections)
// Tile 128x128x16, 256 threads, 8x8 per-thread microtile.
// ---------------------------------------------------------------------------
__global__ __launch_bounds__(256) void gemm_kernel(
    const float* __restrict__ A, const float* __restrict__ W,
    const float* __restrict__ bias, const int* __restrict__ pos,
    float* __restrict__ out, int mode)
{
    __shared__ float As[16][132];
    __shared__ float Bs[16][132];

    const int K = DD;
    const int tid = threadIdx.x;
    const int m0 = blockIdx.y * 128;
    const int n0 = blockIdx.x * 128;
    const int tx = tid & 15;
    const int ty = tid >> 4;

    float acc[8][8];
    #pragma unroll
    for (int i = 0; i < 8; ++i)
        #pragma unroll
        for (int j = 0; j < 8; ++j) acc[i][j] = 0.f;

    for (int k0 = 0; k0 < K; k0 += 16) {
        #pragma unroll
        for (int l = 0; l < 2; ++l) {
            int idx = tid + l * 256;          // 0..511
            int row = idx >> 2;               // 0..127
            int col = (idx & 3) << 2;         // 0,4,8,12
            float4 a = *(const float4*)&A[(size_t)(m0 + row) * K + k0 + col];
            As[col + 0][row] = a.x;
            As[col + 1][row] = a.y;
            As[col + 2][row] = a.z;
            As[col + 3][row] = a.w;
            float4 b = *(const float4*)&W[(size_t)(n0 + row) * K + k0 + col];
            Bs[col + 0][row] = b.x;
            Bs[col + 1][row] = b.y;
            Bs[col + 2][row] = b.z;
            Bs[col + 3][row] = b.w;
        }
        __syncthreads();

        #pragma unroll
        for (int k = 0; k < 16; ++k) {
            float4 a0 = *(const float4*)&As[k][ty * 4];
            float4 a1 = *(const float4*)&As[k][64 + ty * 4];
            float4 b0 = *(const float4*)&Bs[k][tx * 4];
            float4 b1 = *(const float4*)&Bs[k][64 + tx * 4];
            float av[8] = {a0.x, a0.y, a0.z, a0.w, a1.x, a1.y, a1.z, a1.w};
            float bv[8] = {b0.x, b0.y, b0.z, b0.w, b1.x, b1.y, b1.z, b1.w};
            #pragma unroll
            for (int i = 0; i < 8; ++i)
                #pragma unroll
                for (int j = 0; j < 8; ++j)
                    acc[i][j] += av[i] * bv[j];
        }
        __syncthreads();
    }

    // ---- epilogue ----
    float bvals[8];
    #pragma unroll
    for (int j = 0; j < 8; ++j) {
        int c = n0 + ((j < 4) ? (tx * 4 + j) : (64 + tx * 4 + (j - 4)));
        bvals[j] = bias[c];
    }

    // RoPE inv_freq: theta^{-2i/dk} with c_local = 2i (even) -> exp(-c*ln(10000)/64)
    float invf[4];
    if (mode == 2) {
        const float KF = 0.14391157f; // ln(10000)/64
        int cl0 = (n0 + tx * 4) & 63;
        int cl1 = (n0 + 64 + tx * 4) & 63;
        invf[0] = expf(-(float)cl0 * KF);
        invf[1] = expf(-(float)(cl0 + 2) * KF);
        invf[2] = expf(-(float)cl1 * KF);
        invf[3] = expf(-(float)(cl1 + 2) * KF);
    }

    #pragma unroll
    for (int i = 0; i < 8; ++i) {
        int r = (i < 4) ? (ty * 4 + i) : (64 + ty * 4 + (i - 4));
        int gm = m0 + r;
        float v[8];
        #pragma unroll
        for (int j = 0; j < 8; ++j) v[j] = acc[i][j] + bvals[j];

        if (mode == 2) {
            float pf = (float)pos[gm];
            float sn, cs, e, od;
            sincosf(pf * invf[0], &sn, &cs);
            e = v[0] * cs - v[1] * sn; od = v[0] * sn + v[1] * cs; v[0] = e; v[1] = od;
            sincosf(pf * invf[1], &sn, &cs);
            e = v[2] * cs - v[3] * sn; od = v[2] * sn + v[3] * cs; v[2] = e; v[3] = od;
            sincosf(pf * invf[2], &sn, &cs);
            e = v[4] * cs - v[5] * sn; od = v[4] * sn + v[5] * cs; v[4] = e; v[5] = od;
            sincosf(pf * invf[3], &sn, &cs);
            e = v[6] * cs - v[7] * sn; od = v[6] * sn + v[7] * cs; v[6] = e; v[7] = od;
        }

        if (mode == 0) {
            *(float4*)&out[(size_t)gm * DD + n0 + tx * 4] =
                make_float4(v[0], v[1], v[2], v[3]);
            *(float4*)&out[(size_t)gm * DD + n0 + 64 + tx * 4] =
                make_float4(v[4], v[5], v[6], v[7]);
        } else {
            int bb = gm >> 11;          // / SS
            int srow = gm & (SS - 1);
            int c = n0 + tx * 4;
            int h = c >> 6, cl = c & 63;
            *(float4*)&out[(((size_t)(bb * HH + h) * SS + srow) * DKK) + cl] =
                make_float4(v[0], v[1], v[2], v[3]);
            c = n0 + 64 + tx * 4;
            h = c >> 6; cl = c & 63;
            *(float4*)&out[(((size_t)(bb * HH + h) * SS + srow) * DKK) + cl] =
                make_float4(v[4], v[5], v[6], v[7]);
        }
    }
}

// ---------------------------------------------------------------------------
// Flash attention (fp32, causal). One block per (q-tile 64, b*h).
// 256 threads; thread (tm=tid/16, tn=tid%16) owns a 4x4 S/P tile and a 4x4
// O tile (rows tm*4+i, cols/dims tn*4+j). Row stats reduced over 16 lanes.
// Output written as [b, s, h*dk] for the final projection GEMM.
// ---------------------------------------------------------------------------
__global__ __launch_bounds__(256) void flash_kernel(
    const float* __restrict__ Qg, const float* __restrict__ Kg,
    const float* __restrict__ Vg, float* __restrict__ Og)
{
    extern __shared__ float smf[];
    float* Qs  = smf;              // [64][64]  Qs[d*64+m]  (d-major)
    float* Kts = Qs + 64 * 64;     // [64][68]  Kts[d*68+n] (d-major, padded)
    float* Vs  = Kts + 64 * 68;    // [64][64]  Vs[n*64+d]
    float* Ps  = Vs + 64 * 64;     // [64][65]  Ps[n*65+m]

    const int qi = (int)(gridDim.x - 1) - (int)blockIdx.x;  // reversed: big tiles first
    const int bh = blockIdx.y;
    const int q0 = qi * 64;
    const float* Qb = Qg + (size_t)bh * SS * DKK;
    const float* Kb = Kg + (size_t)bh * SS * DKK;
    const float* Vb = Vg + (size_t)bh * SS * DKK;

    const int tid = threadIdx.x;
    const int tn = tid & 15;
    const int tm = tid >> 4;
    const int tm4 = tm * 4, tn4 = tn * 4;

    // Load Q tile transposed into Qs[d][m]
    #pragma unroll
    for (int l = 0; l < 4; ++l) {
        int idx = tid + l * 256;
        int row = idx >> 4;
        int c4 = (idx & 15) << 2;
        float4 q = *(const float4*)&Qb[(size_t)(q0 + row) * DKK + c4];
        Qs[(c4 + 0) * 64 + row] = q.x;
        Qs[(c4 + 1) * 64 + row] = q.y;
        Qs[(c4 + 2) * 64 + row] = q.z;
        Qs[(c4 + 3) * 64 + row] = q.w;
    }

    float o[4][4];
    float mrow[4], lrow[4];
    #pragma unroll
    for (int i = 0; i < 4; ++i) {
        mrow[i] = -CUDART_INF_F;
        lrow[i] = 0.f;
        #pragma unroll
        for (int j = 0; j < 4; ++j) o[i][j] = 0.f;
    }

    for (int kt = 0; kt <= qi; ++kt) {
        const int k0 = kt * 64;
        __syncthreads();  // previous iter consumers done (also orders Q load, iter 0)

        #pragma unroll
        for (int l = 0; l < 4; ++l) {
            int idx = tid + l * 256;
            int row = idx >> 4;
            int c4 = (idx & 15) << 2;
            float4 kk = *(const float4*)&Kb[(size_t)(k0 + row) * DKK + c4];
            Kts[(c4 + 0) * 68 + row] = kk.x;
            Kts[(c4 + 1) * 68 + row] = kk.y;
            Kts[(c4 + 2) * 68 + row] = kk.z;
            Kts[(c4 + 3) * 68 + row] = kk.w;
            float4 vv = *(const float4*)&Vb[(size_t)(k0 + row) * DKK + c4];
            *(float4*)&Vs[row * 64 + c4] = vv;
        }
        __syncthreads();

        // S = Q @ K^T  (4x4 per thread)
        float s[4][4];
        #pragma unroll
        for (int i = 0; i < 4; ++i)
            #pragma unroll
            for (int j = 0; j < 4; ++j) s[i][j] = 0.f;

        #pragma unroll 8
        for (int d = 0; d < 64; ++d) {
            float4 qv = *(const float4*)&Qs[d * 64 + tm4];
            float4 kv = *(const float4*)&Kts[d * 68 + tn4];
            float qa[4] = {qv.x, qv.y, qv.z, qv.w};
            float ka[4] = {kv.x, kv.y, kv.z, kv.w};
            #pragma unroll
            for (int i = 0; i < 4; ++i)
                #pragma unroll
                for (int j = 0; j < 4; ++j)
                    s[i][j] += qa[i] * ka[j];
        }

        const float sc = 0.125f;  // 1/sqrt(64)
        if (kt == qi) {
            #pragma unroll
            for (int i = 0; i < 4; ++i)
                #pragma unroll
                for (int j = 0; j < 4; ++j)
                    s[i][j] = (tn4 + j <= tm4 + i) ? s[i][j] * sc : -CUDART_INF_F;
        } else {
            #pragma unroll
            for (int i = 0; i < 4; ++i)
                #pragma unroll
                for (int j = 0; j < 4; ++j) s[i][j] *= sc;
        }

        // Online softmax per row (row owned by 16 lanes sharing tm)
        #pragma unroll
        for (int i = 0; i < 4; ++i) {
            float rm = fmaxf(fmaxf(s[i][0], s[i][1]), fmaxf(s[i][2], s[i][3]));
            #pragma unroll
            for (int off = 8; off > 0; off >>= 1)
                rm = fmaxf(rm, __shfl_xor_sync(0xffffffffu, rm, off, 16));
            float mnew = fmaxf(mrow[i], rm);
            float corr = __expf(mrow[i] - mnew);
            float rs = 0.f;
            #pragma unroll
            for (int j = 0; j < 4; ++j) {
                s[i][j] = __expf(s[i][j] - mnew);
                rs += s[i][j];
            }
            #pragma unroll
            for (int off = 8; off > 0; off >>= 1)
                rs += __shfl_xor_sync(0xffffffffu, rs, off, 16);
            lrow[i] = lrow[i] * corr + rs;
            mrow[i] = mnew;
            #pragma unroll
            for (int j = 0; j < 4; ++j) o[i][j] *= corr;
        }

        // Stage P transposed: Ps[n][m]
        #pragma unroll
        for (int j = 0; j < 4; ++j)
            #pragma unroll
            for (int i = 0; i < 4; ++i)
                Ps[(tn4 + j) * 65 + tm4 + i] = s[i][j];
        __syncthreads();

        // O += P @ V
        #pragma unroll 8
        for (int n = 0; n < 64; ++n) {
            float p0 = Ps[n * 65 + tm4 + 0];
            float p1 = Ps[n * 65 + tm4 + 1];
            float p2 = Ps[n * 65 + tm4 + 2];
            float p3 = Ps[n * 65 + tm4 + 3];
            float4 v = *(const float4*)&Vs[n * 64 + tn4];
            o[0][0] += p0 * v.x; o[0][1] += p0 * v.y; o[0][2] += p0 * v.z; o[0][3] += p0 * v.w;
            o[1][0] += p1 * v.x; o[1][1] += p1 * v.y; o[1][2] += p1 * v.z; o[1][3] += p1 * v.w;
            o[2][0] += p2 * v.x; o[2][1] += p2 * v.y; o[2][2] += p2 * v.z; o[2][3] += p2 * v.w;
            o[3][0] += p3 * v.x; o[3][1] += p3 * v.y; o[3][2] += p3 * v.z; o[3][3] += p3 * v.w;
        }
    }

    // Normalize and store to [b, s, h*dk]
    const int b = bh >> 4;
    const int h = bh & 15;
    #pragma unroll
    for (int i = 0; i < 4; ++i) {
        float inv = 1.0f / lrow[i];
        int rowg = q0 + tm4 + i;
        *(float4*)&Og[((size_t)(b * SS + rowg)) * DD + h * 64 + tn4] =
            make_float4(o[i][0] * inv, o[i][1] * inv, o[i][2] * inv, o[i][3] * inv);
    }
}

// ---------------------------------------------------------------------------

extern "C" void kernel_launch(void* const* d_in, const int* in_sizes, int n_in,
                              void* d_out, int out_size)
{
    const float* x  = (const float*)d_in[0];
    const float* Wq = (const float*)d_in[1];
    const float* bq = (const float*)d_in[2];
    const float* Wk = (const float*)d_in[3];
    const float* bk = (const float*)d_in[4];
    const float* Wv = (const float*)d_in[5];
    const float* bv = (const float*)d_in[6];
    const float* Wo = (const float*)d_in[7];
    const float* bo = (const float*)d_in[8];
    const int*   pos = (const int*)d_in[9];
    float* out = (float*)d_out;

    float *qp, *kp, *vp, *ap;
    cudaGetSymbolAddress((void**)&qp, g_q);
    cudaGetSymbolAddress((void**)&kp, g_k);
    cudaGetSymbolAddress((void**)&vp, g_v);
    cudaGetSymbolAddress((void**)&ap, g_attn);

    dim3 gp(DD / 128, MM / 128);  // (8, 32)

    gemm_kernel<<<gp, 256>>>(x, Wq, bq, pos, qp, 2);
    gemm_kernel<<<gp, 256>>>(x, Wk, bk, pos, kp, 2);
    gemm_kernel<<<gp, 256>>>(x, Wv, bv, pos, vp, 1);

    const int FLASH_SMEM = (64 * 64 + 64 * 68 + 64 * 64 + 64 * 65) * 4; // 66816 B
    cudaFuncSetAttribute(flash_kernel,
                         cudaFuncAttributeMaxDynamicSharedMemorySize, FLASH_SMEM);
    flash_kernel<<<dim3(SS / 64, BB * HH), 256, FLASH_SMEM>>>(qp, kp, vp, ap);

    gemm_kernel<<<gp, 256>>>(ap, Wo, bo, nullptr, out, 0);
}

// round 2
// speedup vs baseline: 1.5498x; 1.5498x over previous
#include <cuda_runtime.h>
#include <math_constants.h>
#include <cstdint>

// Problem constants (fixed by setup_inputs)
#define BB 2
#define SS 2048
#define HH 16
#define DKK 64
#define DD 1024
#define MM (BB*SS)   // 4096

// Scratch (allocation-free rule: __device__ globals)
__device__ float g_q[(size_t)MM * DD];
__device__ float g_k[(size_t)MM * DD];
__device__ float g_v[(size_t)MM * DD];
__device__ float g_attn[(size_t)MM * DD];
__device__ float g_xt[(size_t)MM * DD];          // tf32-rounded x
__device__ float g_wt[4 * (size_t)DD * DD];      // tf32-rounded Wq,Wk,Wv,Wo

__device__ __forceinline__ float tf32_round(float x) {
    unsigned u;
    asm("cvt.rna.tf32.f32 %0, %1;" : "=r"(u) : "f"(x));
    return __uint_as_float(u);
}

// ---------------------------------------------------------------------------
// Elementwise tf32 rounding prepass (float4 vectorized). n must be /1024.
// ---------------------------------------------------------------------------
__global__ __launch_bounds__(256) void cvt_tf32_kernel(
    const float4* __restrict__ in, float4* __restrict__ out)
{
    int i = blockIdx.x * blockDim.x + threadIdx.x;
    float4 v = in[i];
    v.x = tf32_round(v.x);
    v.y = tf32_round(v.y);
    v.z = tf32_round(v.z);
    v.w = tf32_round(v.w);
    out[i] = v;
}

// ---------------------------------------------------------------------------
// tf32 tensor-core SGEMM: C[M,N] = A[M,K] @ W[N,K]^T + bias
// A, W pre-rounded to tf32. Block tile 128x128, k-chunk 32, cp.async double
// buffer. 256 threads = 8 warps in 2(M)x4(N) grid; warp tile 64x32; each warp
// 4x4 grid of m16n8k8 mma.
// mode 0: out[m*N+n]; mode 1: [b,h,s,dk]; mode 2: [b,h,s,dk] + RoPE.
// ---------------------------------------------------------------------------
#define GS_A 4608              // 128*36 floats
#define GS_BUF 9216            // A+B per stage
#define GEMM_SMEM (2 * GS_BUF * 4)

__device__ __forceinline__ void cp_async16(uint32_t dst, const void* src) {
    asm volatile("cp.async.cg.shared.global [%0], [%1], 16;\n" :: "r"(dst), "l"(src));
}

__global__ __launch_bounds__(256, 2) void gemm_tc_kernel(
    const float* __restrict__ A, const float* __restrict__ W,
    const float* __restrict__ bias, const int* __restrict__ pos,
    float* __restrict__ out, int mode)
{
    extern __shared__ float smem[];
    const uint32_t smem_u32 = (uint32_t)__cvta_generic_to_shared(smem);

    const int K = DD;
    const int tid = threadIdx.x;
    const int lane = tid & 31;
    const int wid = tid >> 5;
    const int g = lane >> 2;      // 0..7
    const int t = lane & 3;       // 0..3
    const int wm0 = (wid & 1) * 64;
    const int wn0 = (wid >> 1) * 32;
    const int m0 = blockIdx.y * 128;
    const int n0 = blockIdx.x * 128;

    // per-thread cp.async unit decomposition (8 units of 16B per chunk)
    int urow[8], ukq[8], uisB[8];
    #pragma unroll
    for (int s = 0; s < 8; ++s) {
        int u = tid + s * 256;          // 0..2047
        uisB[s] = u >> 10;
        int v = u & 1023;
        urow[s] = v >> 3;
        ukq[s]  = v & 7;
    }

    float d[4][4][4];
    #pragma unroll
    for (int mt = 0; mt < 4; ++mt)
        #pragma unroll
        for (int nt = 0; nt < 4; ++nt)
            #pragma unroll
            for (int e = 0; e < 4; ++e) d[mt][nt][e] = 0.f;

    const int NC = K / 32;  // 32 chunks

    // prologue: chunk 0 -> buf 0
    #pragma unroll
    for (int s = 0; s < 8; ++s) {
        const float* src = (uisB[s] ? &W[(size_t)(n0 + urow[s]) * K]
                                    : &A[(size_t)(m0 + urow[s]) * K]) + ukq[s] * 4;
        uint32_t dst = smem_u32 + (uint32_t)((uisB[s] * GS_A + urow[s] * 36 + ukq[s] * 4) * 4);
        cp_async16(dst, src);
    }
    asm volatile("cp.async.commit_group;\n" ::);
    asm volatile("cp.async.wait_group 0;\n" ::);
    __syncthreads();

    for (int kc = 0; kc < NC; ++kc) {
        const int buf = kc & 1;
        if (kc + 1 < NC) {
            const int k0n = (kc + 1) * 32;
            const uint32_t base = smem_u32 + (uint32_t)((buf ^ 1) * GS_BUF * 4);
            #pragma unroll
            for (int s = 0; s < 8; ++s) {
                const float* src = (uisB[s] ? &W[(size_t)(n0 + urow[s]) * K]
                                            : &A[(size_t)(m0 + urow[s]) * K]) + k0n + ukq[s] * 4;
                uint32_t dst = base + (uint32_t)((uisB[s] * GS_A + urow[s] * 36 + ukq[s] * 4) * 4);
                cp_async16(dst, src);
            }
            asm volatile("cp.async.commit_group;\n" ::);
        }

        const float* Sa = smem + buf * GS_BUF;
        const float* Sb = Sa + GS_A;

        #pragma unroll
        for (int k8 = 0; k8 < 32; k8 += 8) {
            uint32_t a[4][4], b[4][2];
            #pragma unroll
            for (int mt = 0; mt < 4; ++mt) {
                const float* pa = Sa + (wm0 + mt * 16 + g) * 36 + k8 + t;
                a[mt][0] = __float_as_uint(pa[0]);
                a[mt][1] = __float_as_uint(pa[8 * 36]);
                a[mt][2] = __float_as_uint(pa[4]);
                a[mt][3] = __float_as_uint(pa[8 * 36 + 4]);
            }
            #pragma unroll
            for (int nt = 0; nt < 4; ++nt) {
                const float* pb = Sb + (wn0 + nt * 8 + g) * 36 + k8 + t;
                b[nt][0] = __float_as_uint(pb[0]);
                b[nt][1] = __float_as_uint(pb[4]);
            }
            #pragma unroll
            for (int mt = 0; mt < 4; ++mt)
                #pragma unroll
                for (int nt = 0; nt < 4; ++nt) {
                    asm volatile(
                        "mma.sync.aligned.m16n8k8.row.col.f32.tf32.tf32.f32 "
                        "{%0,%1,%2,%3}, {%4,%5,%6,%7}, {%8,%9}, {%0,%1,%2,%3};\n"
                        : "+f"(d[mt][nt][0]), "+f"(d[mt][nt][1]),
                          "+f"(d[mt][nt][2]), "+f"(d[mt][nt][3])
                        : "r"(a[mt][0]), "r"(a[mt][1]), "r"(a[mt][2]), "r"(a[mt][3]),
                          "r"(b[nt][0]), "r"(b[nt][1]));
                }
        }

        if (kc + 1 < NC) {
            asm volatile("cp.async.wait_group 0;\n" ::);
            __syncthreads();
        }
    }

    // ---- epilogue ----
    const float KF = 0.14391157f;  // ln(10000)/64

    #pragma unroll
    for (int mt = 0; mt < 4; ++mt) {
        int r0 = m0 + wm0 + mt * 16 + g;
        int r1 = r0 + 8;
        float p0 = 0.f, p1 = 0.f;
        if (mode == 2) {
            p0 = (float)pos[r0];
            p1 = (float)pos[r1];
        }
        #pragma unroll
        for (int nt = 0; nt < 4; ++nt) {
            int c = n0 + wn0 + nt * 8 + 2 * t;
            float bv0 = bias[c], bv1 = bias[c + 1];
            float v00 = d[mt][nt][0] + bv0;
            float v01 = d[mt][nt][1] + bv1;
            float v10 = d[mt][nt][2] + bv0;
            float v11 = d[mt][nt][3] + bv1;

            if (mode == 2) {
                float invf = expf(-(float)(c & 63) * KF);
                float sn, cs, e, od;
                sincosf(p0 * invf, &sn, &cs);
                e = v00 * cs - v01 * sn; od = v00 * sn + v01 * cs; v00 = e; v01 = od;
                sincosf(p1 * invf, &sn, &cs);
                e = v10 * cs - v11 * sn; od = v10 * sn + v11 * cs; v10 = e; v11 = od;
            }

            if (mode == 0) {
                *(float2*)&out[(size_t)r0 * DD + c] = make_float2(v00, v01);
                *(float2*)&out[(size_t)r1 * DD + c] = make_float2(v10, v11);
            } else {
                int h = c >> 6, cl = c & 63;
                int b0i = r0 >> 11, s0 = r0 & (SS - 1);
                int b1i = r1 >> 11, s1 = r1 & (SS - 1);
                *(float2*)&out[(((size_t)(b0i * HH + h) * SS + s0) * DKK) + cl] =
                    make_float2(v00, v01);
                *(float2*)&out[(((size_t)(b1i * HH + h) * SS + s1) * DKK) + cl] =
                    make_float2(v10, v11);
            }
        }
    }
}

// ---------------------------------------------------------------------------
// Flash attention (fp32, causal). One block per (q-tile 64, b*h).
// Output written as [b, s, h*dk], pre-rounded to tf32 for the Wo GEMM.
// ---------------------------------------------------------------------------
__global__ __launch_bounds__(256) void flash_kernel(
    const float* __restrict__ Qg, const float* __restrict__ Kg,
    const float* __restrict__ Vg, float* __restrict__ Og)
{
    extern __shared__ float smf[];
    float* Qs  = smf;              // [64][64]  Qs[d*64+m]  (d-major)
    float* Kts = Qs + 64 * 64;     // [64][68]  Kts[d*68+n] (d-major, padded)
    float* Vs  = Kts + 64 * 68;    // [64][64]  Vs[n*64+d]
    float* Ps  = Vs + 64 * 64;     // [64][65]  Ps[n*65+m]

    const int qi = (int)(gridDim.x - 1) - (int)blockIdx.x;  // reversed: big tiles first
    const int bh = blockIdx.y;
    const int q0 = qi * 64;
    const float* Qb = Qg + (size_t)bh * SS * DKK;
    const float* Kb = Kg + (size_t)bh * SS * DKK;
    const float* Vb = Vg + (size_t)bh * SS * DKK;

    const int tid = threadIdx.x;
    const int tn = tid & 15;
    const int tm = tid >> 4;
    const int tm4 = tm * 4, tn4 = tn * 4;

    #pragma unroll
    for (int l = 0; l < 4; ++l) {
        int idx = tid + l * 256;
        int row = idx >> 4;
        int c4 = (idx & 15) << 2;
        float4 q = *(const float4*)&Qb[(size_t)(q0 + row) * DKK + c4];
        Qs[(c4 + 0) * 64 + row] = q.x;
        Qs[(c4 + 1) * 64 + row] = q.y;
        Qs[(c4 + 2) * 64 + row] = q.z;
        Qs[(c4 + 3) * 64 + row] = q.w;
    }

    float o[4][4];
    float mrow[4], lrow[4];
    #pragma unroll
    for (int i = 0; i < 4; ++i) {
        mrow[i] = -CUDART_INF_F;
        lrow[i] = 0.f;
        #pragma unroll
        for (int j = 0; j < 4; ++j) o[i][j] = 0.f;
    }

    for (int kt = 0; kt <= qi; ++kt) {
        const int k0 = kt * 64;
        __syncthreads();

        #pragma unroll
        for (int l = 0; l < 4; ++l) {
            int idx = tid + l * 256;
            int row = idx >> 4;
            int c4 = (idx & 15) << 2;
            float4 kk = *(const float4*)&Kb[(size_t)(k0 + row) * DKK + c4];
            Kts[(c4 + 0) * 68 + row] = kk.x;
            Kts[(c4 + 1) * 68 + row] = kk.y;
            Kts[(c4 + 2) * 68 + row] = kk.z;
            Kts[(c4 + 3) * 68 + row] = kk.w;
            float4 vv = *(const float4*)&Vb[(size_t)(k0 + row) * DKK + c4];
            *(float4*)&Vs[row * 64 + c4] = vv;
        }
        __syncthreads();

        float s[4][4];
        #pragma unroll
        for (int i = 0; i < 4; ++i)
            #pragma unroll
            for (int j = 0; j < 4; ++j) s[i][j] = 0.f;

        #pragma unroll 8
        for (int d = 0; d < 64; ++d) {
            float4 qv = *(const float4*)&Qs[d * 64 + tm4];
            float4 kv = *(const float4*)&Kts[d * 68 + tn4];
            float qa[4] = {qv.x, qv.y, qv.z, qv.w};
            float ka[4] = {kv.x, kv.y, kv.z, kv.w};
            #pragma unroll
            for (int i = 0; i < 4; ++i)
                #pragma unroll
                for (int j = 0; j < 4; ++j)
                    s[i][j] += qa[i] * ka[j];
        }

        const float sc = 0.125f;
        if (kt == qi) {
            #pragma unroll
            for (int i = 0; i < 4; ++i)
                #pragma unroll
                for (int j = 0; j < 4; ++j)
                    s[i][j] = (tn4 + j <= tm4 + i) ? s[i][j] * sc : -CUDART_INF_F;
        } else {
            #pragma unroll
            for (int i = 0; i < 4; ++i)
                #pragma unroll
                for (int j = 0; j < 4; ++j) s[i][j] *= sc;
        }

        #pragma unroll
        for (int i = 0; i < 4; ++i) {
            float rm = fmaxf(fmaxf(s[i][0], s[i][1]), fmaxf(s[i][2], s[i][3]));
            #pragma unroll
            for (int off = 8; off > 0; off >>= 1)
                rm = fmaxf(rm, __shfl_xor_sync(0xffffffffu, rm, off, 16));
            float mnew = fmaxf(mrow[i], rm);
            float corr = __expf(mrow[i] - mnew);
            float rs = 0.f;
            #pragma unroll
            for (int j = 0; j < 4; ++j) {
                s[i][j] = __expf(s[i][j] - mnew);
                rs += s[i][j];
            }
            #pragma unroll
            for (int off = 8; off > 0; off >>= 1)
                rs += __shfl_xor_sync(0xffffffffu, rs, off, 16);
            lrow[i] = lrow[i] * corr + rs;
            mrow[i] = mnew;
            #pragma unroll
            for (int j = 0; j < 4; ++j) o[i][j] *= corr;
        }

        #pragma unroll
        for (int j = 0; j < 4; ++j)
            #pragma unroll
            for (int i = 0; i < 4; ++i)
                Ps[(tn4 + j) * 65 + tm4 + i] = s[i][j];
        __syncthreads();

        #pragma unroll 8
        for (int n = 0; n < 64; ++n) {
            float p0 = Ps[n * 65 + tm4 + 0];
            float p1 = Ps[n * 65 + tm4 + 1];
            float p2 = Ps[n * 65 + tm4 + 2];
            float p3 = Ps[n * 65 + tm4 + 3];
            float4 v = *(const float4*)&Vs[n * 64 + tn4];
            o[0][0] += p0 * v.x; o[0][1] += p0 * v.y; o[0][2] += p0 * v.z; o[0][3] += p0 * v.w;
            o[1][0] += p1 * v.x; o[1][1] += p1 * v.y; o[1][2] += p1 * v.z; o[1][3] += p1 * v.w;
            o[2][0] += p2 * v.x; o[2][1] += p2 * v.y; o[2][2] += p2 * v.z; o[2][3] += p2 * v.w;
            o[3][0] += p3 * v.x; o[3][1] += p3 * v.y; o[3][2] += p3 * v.z; o[3][3] += p3 * v.w;
        }
    }

    const int b = bh >> 4;
    const int h = bh & 15;
    #pragma unroll
    for (int i = 0; i < 4; ++i) {
        float inv = 1.0f / lrow[i];
        int rowg = q0 + tm4 + i;
        // pre-round to tf32 (RNA) so the Wo GEMM's mma sees rounded inputs
        *(float4*)&Og[((size_t)(b * SS + rowg)) * DD + h * 64 + tn4] =
            make_float4(tf32_round(o[i][0] * inv), tf32_round(o[i][1] * inv),
                        tf32_round(o[i][2] * inv), tf32_round(o[i][3] * inv));
    }
}

// ---------------------------------------------------------------------------

extern "C" void kernel_launch(void* const* d_in, const int* in_sizes, int n_in,
                              void* d_out, int out_size)
{
    const float* x  = (const float*)d_in[0];
    const float* Wq = (const float*)d_in[1];
    const float* bq = (const float*)d_in[2];
    const float* Wk = (const float*)d_in[3];
    const float* bk = (const float*)d_in[4];
    const float* Wv = (const float*)d_in[5];
    const float* bv = (const float*)d_in[6];
    const float* Wo = (const float*)d_in[7];
    const float* bo = (const float*)d_in[8];
    const int*   pos = (const int*)d_in[9];
    float* out = (float*)d_out;

    float *qp, *kp, *vp, *ap, *xt, *wt;
    cudaGetSymbolAddress((void**)&qp, g_q);
    cudaGetSymbolAddress((void**)&kp, g_k);
    cudaGetSymbolAddress((void**)&vp, g_v);
    cudaGetSymbolAddress((void**)&ap, g_attn);
    cudaGetSymbolAddress((void**)&xt, g_xt);
    cudaGetSymbolAddress((void**)&wt, g_wt);
    float* wtq = wt;
    float* wtk = wt + (size_t)DD * DD;
    float* wtv = wt + 2 * (size_t)DD * DD;
    float* wto = wt + 3 * (size_t)DD * DD;

    // tf32 rounding prepass
    cvt_tf32_kernel<<<(MM * DD) / 1024, 256>>>((const float4*)x,  (float4*)xt);
    cvt_tf32_kernel<<<(DD * DD) / 1024, 256>>>((const float4*)Wq, (float4*)wtq);
    cvt_tf32_kernel<<<(DD * DD) / 1024, 256>>>((const float4*)Wk, (float4*)wtk);
    cvt_tf32_kernel<<<(DD * DD) / 1024, 256>>>((const float4*)Wv, (float4*)wtv);
    cvt_tf32_kernel<<<(DD * DD) / 1024, 256>>>((const float4*)Wo, (float4*)wto);

    cudaFuncSetAttribute(gemm_tc_kernel,
                         cudaFuncAttributeMaxDynamicSharedMemorySize, GEMM_SMEM);
    dim3 gp(DD / 128, MM / 128);  // (8, 32)

    gemm_tc_kernel<<<gp, 256, GEMM_SMEM>>>(xt, wtq, bq, pos, qp, 2);
    gemm_tc_kernel<<<gp, 256, GEMM_SMEM>>>(xt, wtk, bk, pos, kp, 2);
    gemm_tc_kernel<<<gp, 256, GEMM_SMEM>>>(xt, wtv, bv, pos, vp, 1);

    const int FLASH_SMEM = (64 * 64 + 64 * 68 + 64 * 64 + 64 * 65) * 4; // 66816 B
    cudaFuncSetAttribute(flash_kernel,
                         cudaFuncAttributeMaxDynamicSharedMemorySize, FLASH_SMEM);
    flash_kernel<<<dim3(SS / 64, BB * HH), 256, FLASH_SMEM>>>(qp, kp, vp, ap);

    gemm_tc_kernel<<<gp, 256, GEMM_SMEM>>>(ap, wto, bo, nullptr, out, 0);
}

// round 3
// speedup vs baseline: 3.0178x; 1.9472x over previous
#include <cuda_runtime.h>
#include <math_constants.h>
#include <cstdint>

// Problem constants (fixed by setup_inputs)
#define BB 2
#define SS 2048
#define HH 16
#define DKK 64
#define DD 1024
#define MM (BB*SS)   // 4096

// Scratch (allocation-free rule: __device__ globals)
__device__ float g_q[(size_t)MM * DD];
__device__ float g_k[(size_t)MM * DD];
__device__ float g_v[(size_t)MM * DD];
__device__ float g_attn[(size_t)MM * DD];
__device__ float g_xt[(size_t)MM * DD];          // tf32-rounded x
__device__ float g_wt[4 * (size_t)DD * DD];      // tf32-rounded Wq,Wk,Wv,Wo

__device__ __forceinline__ float tf32_round(float x) {
    unsigned u;
    asm("cvt.rna.tf32.f32 %0, %1;" : "=r"(u) : "f"(x));
    return __uint_as_float(u);
}

__device__ __forceinline__ void mma_tf32(
    float& d0, float& d1, float& d2, float& d3,
    uint32_t a0, uint32_t a1, uint32_t a2, uint32_t a3,
    uint32_t b0, uint32_t b1)
{
    asm volatile(
        "mma.sync.aligned.m16n8k8.row.col.f32.tf32.tf32.f32 "
        "{%0,%1,%2,%3}, {%4,%5,%6,%7}, {%8,%9}, {%0,%1,%2,%3};\n"
        : "+f"(d0), "+f"(d1), "+f"(d2), "+f"(d3)
        : "r"(a0), "r"(a1), "r"(a2), "r"(a3), "r"(b0), "r"(b1));
}

// ---------------------------------------------------------------------------
// Elementwise tf32 rounding prepass (float4 vectorized). n must be /1024.
// ---------------------------------------------------------------------------
__global__ __launch_bounds__(256) void cvt_tf32_kernel(
    const float4* __restrict__ in, float4* __restrict__ out)
{
    int i = blockIdx.x * blockDim.x + threadIdx.x;
    float4 v = in[i];
    v.x = tf32_round(v.x);
    v.y = tf32_round(v.y);
    v.z = tf32_round(v.z);
    v.w = tf32_round(v.w);
    out[i] = v;
}

// ---------------------------------------------------------------------------
// tf32 tensor-core SGEMM: C[M,N] = A[M,K] @ W[N,K]^T + bias   (as round 2)
// ---------------------------------------------------------------------------
#define GS_A 4608              // 128*36 floats
#define GS_BUF 9216            // A+B per stage
#define GEMM_SMEM (2 * GS_BUF * 4)

__device__ __forceinline__ void cp_async16(uint32_t dst, const void* src) {
    asm volatile("cp.async.cg.shared.global [%0], [%1], 16;\n" :: "r"(dst), "l"(src));
}

__global__ __launch_bounds__(256, 2) void gemm_tc_kernel(
    const float* __restrict__ A, const float* __restrict__ W,
    const float* __restrict__ bias, const int* __restrict__ pos,
    float* __restrict__ out, int mode)
{
    extern __shared__ float smem[];
    const uint32_t smem_u32 = (uint32_t)__cvta_generic_to_shared(smem);

    const int K = DD;
    const int tid = threadIdx.x;
    const int lane = tid & 31;
    const int wid = tid >> 5;
    const int g = lane >> 2;
    const int t = lane & 3;
    const int wm0 = (wid & 1) * 64;
    const int wn0 = (wid >> 1) * 32;
    const int m0 = blockIdx.y * 128;
    const int n0 = blockIdx.x * 128;

    int urow[8], ukq[8], uisB[8];
    #pragma unroll
    for (int s = 0; s < 8; ++s) {
        int u = tid + s * 256;
        uisB[s] = u >> 10;
        int v = u & 1023;
        urow[s] = v >> 3;
        ukq[s]  = v & 7;
    }

    float d[4][4][4];
    #pragma unroll
    for (int mt = 0; mt < 4; ++mt)
        #pragma unroll
        for (int nt = 0; nt < 4; ++nt)
            #pragma unroll
            for (int e = 0; e < 4; ++e) d[mt][nt][e] = 0.f;

    const int NC = K / 32;

    #pragma unroll
    for (int s = 0; s < 8; ++s) {
        const float* src = (uisB[s] ? &W[(size_t)(n0 + urow[s]) * K]
                                    : &A[(size_t)(m0 + urow[s]) * K]) + ukq[s] * 4;
        uint32_t dst = smem_u32 + (uint32_t)((uisB[s] * GS_A + urow[s] * 36 + ukq[s] * 4) * 4);
        cp_async16(dst, src);
    }
    asm volatile("cp.async.commit_group;\n" ::);
    asm volatile("cp.async.wait_group 0;\n" ::);
    __syncthreads();

    for (int kc = 0; kc < NC; ++kc) {
        const int buf = kc & 1;
        if (kc + 1 < NC) {
            const int k0n = (kc + 1) * 32;
            const uint32_t base = smem_u32 + (uint32_t)((buf ^ 1) * GS_BUF * 4);
            #pragma unroll
            for (int s = 0; s < 8; ++s) {
                const float* src = (uisB[s] ? &W[(size_t)(n0 + urow[s]) * K]
                                            : &A[(size_t)(m0 + urow[s]) * K]) + k0n + ukq[s] * 4;
                uint32_t dst = base + (uint32_t)((uisB[s] * GS_A + urow[s] * 36 + ukq[s] * 4) * 4);
                cp_async16(dst, src);
            }
            asm volatile("cp.async.commit_group;\n" ::);
        }

        const float* Sa = smem + buf * GS_BUF;
        const float* Sb = Sa + GS_A;

        #pragma unroll
        for (int k8 = 0; k8 < 32; k8 += 8) {
            uint32_t a[4][4], b[4][2];
            #pragma unroll
            for (int mt = 0; mt < 4; ++mt) {
                const float* pa = Sa + (wm0 + mt * 16 + g) * 36 + k8 + t;
                a[mt][0] = __float_as_uint(pa[0]);
                a[mt][1] = __float_as_uint(pa[8 * 36]);
                a[mt][2] = __float_as_uint(pa[4]);
                a[mt][3] = __float_as_uint(pa[8 * 36 + 4]);
            }
            #pragma unroll
            for (int nt = 0; nt < 4; ++nt) {
                const float* pb = Sb + (wn0 + nt * 8 + g) * 36 + k8 + t;
                b[nt][0] = __float_as_uint(pb[0]);
                b[nt][1] = __float_as_uint(pb[4]);
            }
            #pragma unroll
            for (int mt = 0; mt < 4; ++mt)
                #pragma unroll
                for (int nt = 0; nt < 4; ++nt)
                    mma_tf32(d[mt][nt][0], d[mt][nt][1], d[mt][nt][2], d[mt][nt][3],
                             a[mt][0], a[mt][1], a[mt][2], a[mt][3],
                             b[nt][0], b[nt][1]);
        }

        if (kc + 1 < NC) {
            asm volatile("cp.async.wait_group 0;\n" ::);
            __syncthreads();
        }
    }

    const float KF = 0.14391157f;  // ln(10000)/64

    #pragma unroll
    for (int mt = 0; mt < 4; ++mt) {
        int r0 = m0 + wm0 + mt * 16 + g;
        int r1 = r0 + 8;
        float p0 = 0.f, p1 = 0.f;
        if (mode == 2) {
            p0 = (float)pos[r0];
            p1 = (float)pos[r1];
        }
        #pragma unroll
        for (int nt = 0; nt < 4; ++nt) {
            int c = n0 + wn0 + nt * 8 + 2 * t;
            float bv0 = bias[c], bv1 = bias[c + 1];
            float v00 = d[mt][nt][0] + bv0;
            float v01 = d[mt][nt][1] + bv1;
            float v10 = d[mt][nt][2] + bv0;
            float v11 = d[mt][nt][3] + bv1;

            if (mode == 2) {
                float invf = expf(-(float)(c & 63) * KF);
                float sn, cs, e, od;
                sincosf(p0 * invf, &sn, &cs);
                e = v00 * cs - v01 * sn; od = v00 * sn + v01 * cs; v00 = e; v01 = od;
                sincosf(p1 * invf, &sn, &cs);
                e = v10 * cs - v11 * sn; od = v10 * sn + v11 * cs; v10 = e; v11 = od;
            }

            if (mode == 0) {
                *(float2*)&out[(size_t)r0 * DD + c] = make_float2(v00, v01);
                *(float2*)&out[(size_t)r1 * DD + c] = make_float2(v10, v11);
            } else {
                int h = c >> 6, cl = c & 63;
                int b0i = r0 >> 11, s0 = r0 & (SS - 1);
                int b1i = r1 >> 11, s1 = r1 & (SS - 1);
                *(float2*)&out[(((size_t)(b0i * HH + h) * SS + s0) * DKK) + cl] =
                    make_float2(v00, v01);
                *(float2*)&out[(((size_t)(b1i * HH + h) * SS + s1) * DKK) + cl] =
                    make_float2(v10, v11);
            }
        }
    }
}

// ---------------------------------------------------------------------------
// Tensor-core flash attention (tf32 mma, fp32 softmax, causal).
// Block: 128 threads = 4 warps; q-tile 64 rows (warp = 16 rows), kv-tile 64.
// Q kept in registers as mma A-fragments (pre-scaled by 1/8, RNA tf32).
// K,V tiles staged in smem (RNA tf32). P re-fragmented through smem
// (per-warp-private rows -> only __syncwarp needed).
// Output [b, s, h*dk], tf32-rounded for the Wo GEMM.
// ---------------------------------------------------------------------------
#define KS_ST 68
#define VS_ST 72
#define PS_ST 68
#define FLASH_SMEM ((64*KS_ST + 64*VS_ST + 64*PS_ST) * 4)  // 53248 B

__global__ __launch_bounds__(128) void flash_tc_kernel(
    const float* __restrict__ Qg, const float* __restrict__ Kg,
    const float* __restrict__ Vg, float* __restrict__ Og)
{
    extern __shared__ float sm[];
    float* Ks = sm;               // [64][68]  K tile, [seq][d]
    float* Vs = Ks + 64 * KS_ST;  // [64][72]  V tile, [seq][d]
    float* Ps = Vs + 64 * VS_ST;  // [64][68]  P tile (also Q staging), [row][col]

    const int qi = (int)(gridDim.x - 1) - (int)blockIdx.x;  // big tiles first
    const int bh = blockIdx.y;
    const int q0 = qi * 64;
    const float* Qb = Qg + (size_t)bh * SS * DKK;
    const float* Kb = Kg + (size_t)bh * SS * DKK;
    const float* Vb = Vg + (size_t)bh * SS * DKK;

    const int tid = threadIdx.x;
    const int lane = tid & 31;
    const int wid = tid >> 5;
    const int g = lane >> 2;     // 0..7
    const int t = lane & 3;      // 0..3
    const int wr = wid * 16;     // warp row base within tile

    // ---- stage Q (scaled by 1/sqrt(dk), tf32-rounded) into Ps ----
    #pragma unroll
    for (int l = 0; l < 8; ++l) {
        int idx = tid + l * 128;       // 0..1023 float4 units
        int row = idx >> 4;
        int c4 = (idx & 15) << 2;
        float4 q = *(const float4*)&Qb[(size_t)(q0 + row) * DKK + c4];
        q.x = tf32_round(q.x * 0.125f);
        q.y = tf32_round(q.y * 0.125f);
        q.z = tf32_round(q.z * 0.125f);
        q.w = tf32_round(q.w * 0.125f);
        *(float4*)&Ps[row * PS_ST + c4] = q;
    }
    __syncthreads();

    // ---- Q fragments in registers: qf[k8][0..3] ----
    uint32_t qf[8][4];
    #pragma unroll
    for (int k8 = 0; k8 < 8; ++k8) {
        const float* pa = Ps + (wr + g) * PS_ST + k8 * 8 + t;
        qf[k8][0] = __float_as_uint(pa[0]);
        qf[k8][1] = __float_as_uint(pa[8 * PS_ST]);
        qf[k8][2] = __float_as_uint(pa[4]);
        qf[k8][3] = __float_as_uint(pa[8 * PS_ST + 4]);
    }
    __syncthreads();  // Ps free for P use

    float o[8][4];
    #pragma unroll
    for (int nt = 0; nt < 8; ++nt)
        #pragma unroll
        for (int e = 0; e < 4; ++e) o[nt][e] = 0.f;
    float m0 = -CUDART_INF_F, m1 = -CUDART_INF_F;
    float l0 = 0.f, l1 = 0.f;

    for (int kt = 0; kt <= qi; ++kt) {
        const int k0 = kt * 64;

        // ---- load K,V tiles (tf32-rounded) ----
        #pragma unroll
        for (int l = 0; l < 8; ++l) {
            int idx = tid + l * 128;
            int row = idx >> 4;
            int c4 = (idx & 15) << 2;
            float4 kk = *(const float4*)&Kb[(size_t)(k0 + row) * DKK + c4];
            kk.x = tf32_round(kk.x); kk.y = tf32_round(kk.y);
            kk.z = tf32_round(kk.z); kk.w = tf32_round(kk.w);
            *(float4*)&Ks[row * KS_ST + c4] = kk;
            float4 vv = *(const float4*)&Vb[(size_t)(k0 + row) * DKK + c4];
            vv.x = tf32_round(vv.x); vv.y = tf32_round(vv.y);
            vv.z = tf32_round(vv.z); vv.w = tf32_round(vv.w);
            *(float4*)&Vs[row * VS_ST + c4] = vv;
        }
        __syncthreads();

        // ---- S = Q @ K^T ----
        float s[8][4];
        #pragma unroll
        for (int nt = 0; nt < 8; ++nt)
            #pragma unroll
            for (int e = 0; e < 4; ++e) s[nt][e] = 0.f;

        #pragma unroll
        for (int k8 = 0; k8 < 8; ++k8) {
            const float* pk = Ks + g * KS_ST + k8 * 8 + t;
            #pragma unroll
            for (int nt = 0; nt < 8; ++nt) {
                uint32_t b0 = __float_as_uint(pk[nt * 8 * KS_ST]);
                uint32_t b1 = __float_as_uint(pk[nt * 8 * KS_ST + 4]);
                mma_tf32(s[nt][0], s[nt][1], s[nt][2], s[nt][3],
                         qf[k8][0], qf[k8][1], qf[k8][2], qf[k8][3], b0, b1);
            }
        }

        // ---- causal mask on diagonal tile ----
        if (kt == qi) {
            int r0l = wr + g, r1l = r0l + 8;
            #pragma unroll
            for (int nt = 0; nt < 8; ++nt) {
                int c = nt * 8 + 2 * t;
                if (c > r0l)     s[nt][0] = -CUDART_INF_F;
                if (c + 1 > r0l) s[nt][1] = -CUDART_INF_F;
                if (c > r1l)     s[nt][2] = -CUDART_INF_F;
                if (c + 1 > r1l) s[nt][3] = -CUDART_INF_F;
            }
        }

        // ---- online softmax (row quads: lanes sharing g) ----
        float rm0 = s[0][0], rm1 = s[0][2];
        #pragma unroll
        for (int nt = 0; nt < 8; ++nt) {
            rm0 = fmaxf(rm0, fmaxf(s[nt][0], s[nt][1]));
            rm1 = fmaxf(rm1, fmaxf(s[nt][2], s[nt][3]));
        }
        rm0 = fmaxf(rm0, __shfl_xor_sync(0xffffffffu, rm0, 1));
        rm0 = fmaxf(rm0, __shfl_xor_sync(0xffffffffu, rm0, 2));
        rm1 = fmaxf(rm1, __shfl_xor_sync(0xffffffffu, rm1, 1));
        rm1 = fmaxf(rm1, __shfl_xor_sync(0xffffffffu, rm1, 2));

        float mn0 = fmaxf(m0, rm0), mn1 = fmaxf(m1, rm1);
        float corr0 = __expf(m0 - mn0), corr1 = __expf(m1 - mn1);
        float rs0 = 0.f, rs1 = 0.f;
        #pragma unroll
        for (int nt = 0; nt < 8; ++nt) {
            s[nt][0] = __expf(s[nt][0] - mn0);
            s[nt][1] = __expf(s[nt][1] - mn0);
            s[nt][2] = __expf(s[nt][2] - mn1);
            s[nt][3] = __expf(s[nt][3] - mn1);
            rs0 += s[nt][0] + s[nt][1];
            rs1 += s[nt][2] + s[nt][3];
        }
        rs0 += __shfl_xor_sync(0xffffffffu, rs0, 1);
        rs0 += __shfl_xor_sync(0xffffffffu, rs0, 2);
        rs1 += __shfl_xor_sync(0xffffffffu, rs1, 1);
        rs1 += __shfl_xor_sync(0xffffffffu, rs1, 2);
        l0 = l0 * corr0 + rs0;  m0 = mn0;
        l1 = l1 * corr1 + rs1;  m1 = mn1;

        #pragma unroll
        for (int nt = 0; nt < 8; ++nt) {
            o[nt][0] *= corr0; o[nt][1] *= corr0;
            o[nt][2] *= corr1; o[nt][3] *= corr1;
        }

        // ---- P -> smem (per-warp-private rows), tf32-rounded ----
        #pragma unroll
        for (int nt = 0; nt < 8; ++nt) {
            *(float2*)&Ps[(wr + g) * PS_ST + nt * 8 + 2 * t] =
                make_float2(tf32_round(s[nt][0]), tf32_round(s[nt][1]));
            *(float2*)&Ps[(wr + g + 8) * PS_ST + nt * 8 + 2 * t] =
                make_float2(tf32_round(s[nt][2]), tf32_round(s[nt][3]));
        }
        __syncwarp();

        // ---- O += P @ V ----
        #pragma unroll
        for (int k8 = 0; k8 < 8; ++k8) {
            const float* pa = Ps + (wr + g) * PS_ST + k8 * 8 + t;
            uint32_t a0 = __float_as_uint(pa[0]);
            uint32_t a1 = __float_as_uint(pa[8 * PS_ST]);
            uint32_t a2 = __float_as_uint(pa[4]);
            uint32_t a3 = __float_as_uint(pa[8 * PS_ST + 4]);
            const float* pv = Vs + (k8 * 8 + t) * VS_ST + g;
            #pragma unroll
            for (int nt = 0; nt < 8; ++nt) {
                uint32_t b0 = __float_as_uint(pv[nt * 8]);
                uint32_t b1 = __float_as_uint(pv[4 * VS_ST + nt * 8]);
                mma_tf32(o[nt][0], o[nt][1], o[nt][2], o[nt][3],
                         a0, a1, a2, a3, b0, b1);
            }
        }
        __syncthreads();  // before next iteration overwrites Ks/Vs
    }

    // ---- epilogue: normalize, tf32-round, store [b, s, h*dk] ----
    const int b = bh >> 4;
    const int h = bh & 15;
    const float inv0 = 1.0f / l0, inv1 = 1.0f / l1;
    const int r0g = q0 + wr + g, r1g = r0g + 8;
    #pragma unroll
    for (int nt = 0; nt < 8; ++nt) {
        int col = nt * 8 + 2 * t;
        *(float2*)&Og[((size_t)(b * SS + r0g)) * DD + h * 64 + col] =
            make_float2(tf32_round(o[nt][0] * inv0), tf32_round(o[nt][1] * inv0));
        *(float2*)&Og[((size_t)(b * SS + r1g)) * DD + h * 64 + col] =
            make_float2(tf32_round(o[nt][2] * inv1), tf32_round(o[nt][3] * inv1));
    }
}

// ---------------------------------------------------------------------------

extern "C" void kernel_launch(void* const* d_in, const int* in_sizes, int n_in,
                              void* d_out, int out_size)
{
    const float* x  = (const float*)d_in[0];
    const float* Wq = (const float*)d_in[1];
    const float* bq = (const float*)d_in[2];
    const float* Wk = (const float*)d_in[3];
    const float* bk = (const float*)d_in[4];
    const float* Wv = (const float*)d_in[5];
    const float* bv = (const float*)d_in[6];
    const float* Wo = (const float*)d_in[7];
    const float* bo = (const float*)d_in[8];
    const int*   pos = (const int*)d_in[9];
    float* out = (float*)d_out;

    float *qp, *kp, *vp, *ap, *xt, *wt;
    cudaGetSymbolAddress((void**)&qp, g_q);
    cudaGetSymbolAddress((void**)&kp, g_k);
    cudaGetSymbolAddress((void**)&vp, g_v);
    cudaGetSymbolAddress((void**)&ap, g_attn);
    cudaGetSymbolAddress((void**)&xt, g_xt);
    cudaGetSymbolAddress((void**)&wt, g_wt);
    float* wtq = wt;
    float* wtk = wt + (size_t)DD * DD;
    float* wtv = wt + 2 * (size_t)DD * DD;
    float* wto = wt + 3 * (size_t)DD * DD;

    cvt_tf32_kernel<<<(MM * DD) / 1024, 256>>>((const float4*)x,  (float4*)xt);
    cvt_tf32_kernel<<<(DD * DD) / 1024, 256>>>((const float4*)Wq, (float4*)wtq);
    cvt_tf32_kernel<<<(DD * DD) / 1024, 256>>>((const float4*)Wk, (float4*)wtk);
    cvt_tf32_kernel<<<(DD * DD) / 1024, 256>>>((const float4*)Wv, (float4*)wtv);
    cvt_tf32_kernel<<<(DD * DD) / 1024, 256>>>((const float4*)Wo, (float4*)wto);

    cudaFuncSetAttribute(gemm_tc_kernel,
                         cudaFuncAttributeMaxDynamicSharedMemorySize, GEMM_SMEM);
    dim3 gp(DD / 128, MM / 128);  // (8, 32)

    gemm_tc_kernel<<<gp, 256, GEMM_SMEM>>>(xt, wtq, bq, pos, qp, 2);
    gemm_tc_kernel<<<gp, 256, GEMM_SMEM>>>(xt, wtk, bk, pos, kp, 2);
    gemm_tc_kernel<<<gp, 256, GEMM_SMEM>>>(xt, wtv, bv, pos, vp, 1);

    cudaFuncSetAttribute(flash_tc_kernel,
                         cudaFuncAttributeMaxDynamicSharedMemorySize, FLASH_SMEM);
    flash_tc_kernel<<<dim3(SS / 64, BB * HH), 128, FLASH_SMEM>>>(qp, kp, vp, ap);

    gemm_tc_kernel<<<gp, 256, GEMM_SMEM>>>(ap, wto, bo, nullptr, out, 0);
}

// round 5
// speedup vs baseline: 3.1112x; 1.0310x over previous
#include <cuda_runtime.h>
#include <math_constants.h>
#include <cstdint>

// Problem constants (fixed by setup_inputs)
#define BB 2
#define SS 2048
#define HH 16
#define DKK 64
#define DD 1024
#define MM (BB*SS)   // 4096

// Scratch (allocation-free rule: __device__ globals)
__device__ float g_q[(size_t)MM * DD];
__device__ float g_k[(size_t)MM * DD];
__device__ float g_v[(size_t)MM * DD];
__device__ float g_attn[(size_t)MM * DD];
__device__ float g_xt[(size_t)MM * DD];          // tf32-rounded x
__device__ float g_wt[4 * (size_t)DD * DD];      // tf32-rounded Wq,Wk,Wv,Wo (contiguous)
__device__ float2 g_rope[(size_t)MM * 32];       // (cos, sin) per (row, freq)

__device__ __forceinline__ float tf32_round(float x) {
    unsigned u;
    asm("cvt.rna.tf32.f32 %0, %1;" : "=r"(u) : "f"(x));
    return __uint_as_float(u);
}

__device__ __forceinline__ void mma_tf32(
    float& d0, float& d1, float& d2, float& d3,
    uint32_t a0, uint32_t a1, uint32_t a2, uint32_t a3,
    uint32_t b0, uint32_t b1)
{
    asm volatile(
        "mma.sync.aligned.m16n8k8.row.col.f32.tf32.tf32.f32 "
        "{%0,%1,%2,%3}, {%4,%5,%6,%7}, {%8,%9}, {%0,%1,%2,%3};\n"
        : "+f"(d0), "+f"(d1), "+f"(d2), "+f"(d3)
        : "r"(a0), "r"(a1), "r"(a2), "r"(a3), "r"(b0), "r"(b1));
}

__device__ __forceinline__ void cp_async16(uint32_t dst, const void* src) {
    asm volatile("cp.async.cg.shared.global [%0], [%1], 16;\n" :: "r"(dst), "l"(src));
}

// ---------------------------------------------------------------------------
// Merged tf32 rounding prepass: x + 4 weights into g_xt / g_wt.
// ---------------------------------------------------------------------------
__global__ __launch_bounds__(256) void cvt_all_kernel(
    const float4* __restrict__ x,
    const float4* __restrict__ wq, const float4* __restrict__ wk,
    const float4* __restrict__ wv, const float4* __restrict__ wo,
    float4* __restrict__ xt, float4* __restrict__ wt)
{
    const int NX = MM * DD / 4;      // 1048576
    const int NW = DD * DD / 4;      // 262144
    int i = blockIdx.x * 256 + threadIdx.x;
    const float4* src;
    float4* dst;
    int off;
    if (i < NX) { src = x; dst = xt; off = i; }
    else {
        int j = i - NX;
        int w = j >> 18;
        off = j & (NW - 1);
        src = (w == 0) ? wq : (w == 1) ? wk : (w == 2) ? wv : wo;
        dst = wt + (size_t)w * NW;
    }
    float4 v = src[off];
    v.x = tf32_round(v.x); v.y = tf32_round(v.y);
    v.z = tf32_round(v.z); v.w = tf32_round(v.w);
    dst[off] = v;
}

// ---------------------------------------------------------------------------
// RoPE table: rope[m][f] = (cos, sin) of pos[m] * theta^(-2f/64).
// ---------------------------------------------------------------------------
__global__ __launch_bounds__(256) void rope_table_kernel(
    const int* __restrict__ pos, float2* __restrict__ rope)
{
    int i = blockIdx.x * 256 + threadIdx.x;   // 0 .. MM*32-1
    int m = i >> 5, f = i & 31;
    const float KF = 0.14391157f;             // ln(10000)/64
    float invf = expf(-2.0f * (float)f * KF);
    float a = (float)pos[m] * invf;
    float sn, cs;
    sincosf(a, &sn, &cs);
    rope[i] = make_float2(cs, sn);
}

// ---------------------------------------------------------------------------
// tf32 mma GEMM: C[M,N] = A[M,K] @ W[N,K]^T + bias.
// CTA tile 128x128, 128 threads = 4 warps of 64x64, k-chunk 32,
// 3-stage cp.async ring (wait_group 2 = 2-chunk lookahead).
// mode 1: fused QKV (N=3072), writes [b,h,s,dk], RoPE (table) on Q,K,
//         outputs tf32-rounded (so flash needs no per-tile rounding).
// mode 0: Wo, writes out[m*DD + n] (final output, NOT rounded).
// ---------------------------------------------------------------------------
#define GSA 4608               // floats per matrix per stage (128*36)
#define GSTG 9216              // floats per stage (A+B)
#define GNSTG 3
#define GEMM_SMEM (GNSTG * GSTG * 4)   // 110592 B
#define GNC (DD / 32)          // 32 k-chunks

__global__ __launch_bounds__(128) void gemm_tc_kernel(
    const float* __restrict__ A, const float* __restrict__ W,
    const float* __restrict__ bQ, const float* __restrict__ bK,
    const float* __restrict__ bV,
    const float2* __restrict__ rope,
    float* __restrict__ oQ, float* __restrict__ oK, float* __restrict__ oV,
    int mode)
{
    extern __shared__ float smem[];
    const uint32_t smem_u = (uint32_t)__cvta_generic_to_shared(smem);

    const int tid = threadIdx.x;
    const int lane = tid & 31;
    const int wid = tid >> 5;
    const int g = lane >> 2;
    const int t = lane & 3;
    const int wm0 = (wid >> 1) * 64;
    const int wn0 = (wid & 1) * 64;
    const int m0 = blockIdx.y * 128;
    const int n0 = blockIdx.x * 128;

    // loader decomposition: each thread owns 8 A-chunks + 8 B-chunks of 16B
    const int seg = tid & 7;          // 16B segment within 128B row-chunk
    const int rbase = tid >> 3;       // 0..15, rows rbase + 16j
    const float* aoff = A + (size_t)(m0 + rbase) * DD + seg * 4;
    const float* boff = W + (size_t)(n0 + rbase) * DD + seg * 4;
    const uint32_t sdst = (uint32_t)((rbase * 36 + seg * 4) * 4);

    float d[4][8][4];
    #pragma unroll
    for (int mt = 0; mt < 4; ++mt)
        #pragma unroll
        for (int nt = 0; nt < 8; ++nt)
            #pragma unroll
            for (int e = 0; e < 4; ++e) d[mt][nt][e] = 0.f;

    // prologue: chunks 0,1 -> stages 0,1
    #pragma unroll
    for (int p = 0; p < 2; ++p) {
        uint32_t sb = smem_u + p * GSTG * 4 + sdst;
        #pragma unroll
        for (int j = 0; j < 8; ++j) {
            cp_async16(sb + j * (16 * 36 * 4), aoff + (size_t)j * 16 * DD + p * 32);
            cp_async16(sb + GSA * 4 + j * (16 * 36 * 4), boff + (size_t)j * 16 * DD + p * 32);
        }
        asm volatile("cp.async.commit_group;" ::: "memory");
    }

    int stg = 2;           // stage receiving chunk kc+2
    for (int kc = 0; kc < GNC; ++kc) {
        if (kc + 2 < GNC) {
            uint32_t sb = smem_u + stg * GSTG * 4 + sdst;
            const int ko = (kc + 2) * 32;
            #pragma unroll
            for (int j = 0; j < 8; ++j) {
                cp_async16(sb + j * (16 * 36 * 4), aoff + (size_t)j * 16 * DD + ko);
                cp_async16(sb + GSA * 4 + j * (16 * 36 * 4), boff + (size_t)j * 16 * DD + ko);
            }
        }
        asm volatile("cp.async.commit_group;" ::: "memory");
        asm volatile("cp.async.wait_group 2;" ::: "memory");   // chunk kc done
        __syncthreads();

        const int cur = (stg + 1 == GNSTG) ? 0 : stg + 1;      // (kc)%3
        const float* Sa = smem + cur * GSTG;
        const float* Sb = Sa + GSA;

        #pragma unroll
        for (int k8 = 0; k8 < 32; k8 += 8) {
            uint32_t a[4][4], b[8][2];
            #pragma unroll
            for (int mt = 0; mt < 4; ++mt) {
                const float* pa = Sa + (wm0 + mt * 16 + g) * 36 + k8 + t;
                a[mt][0] = __float_as_uint(pa[0]);
                a[mt][1] = __float_as_uint(pa[8 * 36]);
                a[mt][2] = __float_as_uint(pa[4]);
                a[mt][3] = __float_as_uint(pa[8 * 36 + 4]);
            }
            #pragma unroll
            for (int nt = 0; nt < 8; ++nt) {
                const float* pb = Sb + (wn0 + nt * 8 + g) * 36 + k8 + t;
                b[nt][0] = __float_as_uint(pb[0]);
                b[nt][1] = __float_as_uint(pb[4]);
            }
            #pragma unroll
            for (int mt = 0; mt < 4; ++mt)
                #pragma unroll
                for (int nt = 0; nt < 8; ++nt)
                    mma_tf32(d[mt][nt][0], d[mt][nt][1], d[mt][nt][2], d[mt][nt][3],
                             a[mt][0], a[mt][1], a[mt][2], a[mt][3],
                             b[nt][0], b[nt][1]);
        }
        __syncthreads();     // protect stage before it is overwritten
        stg = cur;           // next load target = (kc+3)%3 = (kc)%3 = cur
    }

    // ---- epilogue ----
    #pragma unroll
    for (int mt = 0; mt < 4; ++mt) {
        int r0 = m0 + wm0 + mt * 16 + g;
        int r1 = r0 + 8;
        const float2* rp0 = rope + (size_t)r0 * 32;
        const float2* rp1 = rope + (size_t)r1 * 32;
        #pragma unroll
        for (int nt = 0; nt < 8; ++nt) {
            int c = n0 + wn0 + nt * 8 + 2 * t;
            if (mode == 0) {
                float bv0 = __ldg(bQ + c), bv1 = __ldg(bQ + c + 1);
                *(float2*)&oQ[(size_t)r0 * DD + c] =
                    make_float2(d[mt][nt][0] + bv0, d[mt][nt][1] + bv1);
                *(float2*)&oQ[(size_t)r1 * DD + c] =
                    make_float2(d[mt][nt][2] + bv0, d[mt][nt][3] + bv1);
            } else {
                const int which = c >> 10;        // 0=Q 1=K 2=V
                const int cc = c & 1023;
                const int h = cc >> 6, cl = cc & 63;
                const float* bp = (which == 0) ? bQ : (which == 1) ? bK : bV;
                float* outp = (which == 0) ? oQ : (which == 1) ? oK : oV;
                float bv0 = __ldg(bp + cc), bv1 = __ldg(bp + cc + 1);
                float v00 = d[mt][nt][0] + bv0, v01 = d[mt][nt][1] + bv1;
                float v10 = d[mt][nt][2] + bv0, v11 = d[mt][nt][3] + bv1;
                if (which < 2) {
                    float2 cs0 = rp0[cl >> 1], cs1 = rp1[cl >> 1];
                    float e, od;
                    e  = v00 * cs0.x - v01 * cs0.y;
                    od = v00 * cs0.y + v01 * cs0.x;  v00 = e; v01 = od;
                    e  = v10 * cs1.x - v11 * cs1.y;
                    od = v10 * cs1.y + v11 * cs1.x;  v10 = e; v11 = od;
                }
                int b0i = r0 >> 11, s0 = r0 & (SS - 1);
                int b1i = r1 >> 11, s1 = r1 & (SS - 1);
                *(float2*)&outp[(((size_t)(b0i * HH + h) * SS + s0) * DKK) + cl] =
                    make_float2(tf32_round(v00), tf32_round(v01));
                *(float2*)&outp[(((size_t)(b1i * HH + h) * SS + s1) * DKK) + cl] =
                    make_float2(tf32_round(v10), tf32_round(v11));
            }
        }
    }
}

// ---------------------------------------------------------------------------
// Tensor-core flash attention (tf32 mma, fp32 softmax, causal).
// 128 threads = 4 warps (16 rows each); q-tile 64, kv-tile 64.
// K/V double-buffered via cp.async (inputs pre-rounded by the QKV GEMM).
// ---------------------------------------------------------------------------
#define KS_ST 68
#define VS_ST 72
#define PS_ST 68
#define FK_STG (64*KS_ST + 64*VS_ST)                 // 8960 floats / stage
#define FLASH_SMEM ((2*FK_STG + 64*PS_ST) * 4)       // 89088 B

__global__ __launch_bounds__(128) void flash_tc_kernel(
    const float* __restrict__ Qg, const float* __restrict__ Kg,
    const float* __restrict__ Vg, float* __restrict__ Og)
{
    extern __shared__ float sm[];
    float* Ps = sm + 2 * FK_STG;
    const uint32_t smem_u = (uint32_t)__cvta_generic_to_shared(sm);

    const int qi = (int)(gridDim.x - 1) - (int)blockIdx.x;  // big tiles first
    const int bh = blockIdx.y;
    const int q0 = qi * 64;
    const float* Qb = Qg + (size_t)bh * SS * DKK;
    const float* Kb = Kg + (size_t)bh * SS * DKK;
    const float* Vb = Vg + (size_t)bh * SS * DKK;

    const int tid = threadIdx.x;
    const int lane = tid & 31;
    const int wid = tid >> 5;
    const int g = lane >> 2;
    const int t = lane & 3;
    const int wr = wid * 16;

    // loader decomposition: tile = 64 rows x 16 chunks(16B); 8 chunks/thread/tensor
    const int fr = tid >> 4;          // row base (0..7), rows fr+8j
    const int fc = tid & 15;          // chunk (0..15)
    const float* ksrc = Kb + (size_t)fr * DKK + fc * 4;
    const float* vsrc = Vb + (size_t)fr * DKK + fc * 4;
    const uint32_t kdst = smem_u + (uint32_t)(fr * (KS_ST*4) + fc * 16);
    const uint32_t vdst = smem_u + (uint32_t)(64*KS_ST*4 + fr * (VS_ST*4) + fc * 16);

    // ---- stage Q (scaled by 1/8, RNA tf32) into Ps, build register fragments ----
    #pragma unroll
    for (int l = 0; l < 8; ++l) {
        int idx = tid + l * 128;
        int row = idx >> 4;
        int c4 = (idx & 15) << 2;
        float4 q = *(const float4*)&Qb[(size_t)(q0 + row) * DKK + c4];
        q.x = tf32_round(q.x * 0.125f);
        q.y = tf32_round(q.y * 0.125f);
        q.z = tf32_round(q.z * 0.125f);
        q.w = tf32_round(q.w * 0.125f);
        *(float4*)&Ps[row * PS_ST + c4] = q;
    }

    // prologue: KV tile 0 -> stage 0 (overlaps Q staging)
    #pragma unroll
    for (int j = 0; j < 8; ++j) {
        cp_async16(kdst + j * (8 * KS_ST * 4), ksrc + (size_t)j * 8 * DKK);
        cp_async16(vdst + j * (8 * VS_ST * 4), vsrc + (size_t)j * 8 * DKK);
    }
    asm volatile("cp.async.commit_group;" ::: "memory");

    __syncthreads();
    uint32_t qf[8][4];
    #pragma unroll
    for (int k8 = 0; k8 < 8; ++k8) {
        const float* pa = Ps + (wr + g) * PS_ST + k8 * 8 + t;
        qf[k8][0] = __float_as_uint(pa[0]);
        qf[k8][1] = __float_as_uint(pa[8 * PS_ST]);
        qf[k8][2] = __float_as_uint(pa[4]);
        qf[k8][3] = __float_as_uint(pa[8 * PS_ST + 4]);
    }
    __syncthreads();  // Ps free for P use

    float o[8][4];
    #pragma unroll
    for (int nt = 0; nt < 8; ++nt)
        #pragma unroll
        for (int e = 0; e < 4; ++e) o[nt][e] = 0.f;
    float m0 = -CUDART_INF_F, m1 = -CUDART_INF_F;
    float l0 = 0.f, l1 = 0.f;

    for (int kt = 0; kt <= qi; ++kt) {
        // prefetch next KV tile into the other stage
        if (kt < qi) {
            uint32_t so = (uint32_t)(((kt + 1) & 1) * FK_STG * 4);
            const size_t go = (size_t)(kt + 1) * 64 * DKK;
            #pragma unroll
            for (int j = 0; j < 8; ++j) {
                cp_async16(kdst + so + j * (8 * KS_ST * 4), ksrc + go + (size_t)j * 8 * DKK);
                cp_async16(vdst + so + j * (8 * VS_ST * 4), vsrc + go + (size_t)j * 8 * DKK);
            }
        }
        asm volatile("cp.async.commit_group;" ::: "memory");
        asm volatile("cp.async.wait_group 1;" ::: "memory");   // tile kt ready
        __syncthreads();

        const float* Ks = sm + (kt & 1) * FK_STG;
        const float* Vs = Ks + 64 * KS_ST;

        // ---- S = Q @ K^T ----
        float s[8][4];
        #pragma unroll
        for (int nt = 0; nt < 8; ++nt)
            #pragma unroll
            for (int e = 0; e < 4; ++e) s[nt][e] = 0.f;

        #pragma unroll
        for (int k8 = 0; k8 < 8; ++k8) {
            const float* pk = Ks + g * KS_ST + k8 * 8 + t;
            #pragma unroll
            for (int nt = 0; nt < 8; ++nt) {
                uint32_t b0 = __float_as_uint(pk[nt * 8 * KS_ST]);
                uint32_t b1 = __float_as_uint(pk[nt * 8 * KS_ST + 4]);
                mma_tf32(s[nt][0], s[nt][1], s[nt][2], s[nt][3],
                         qf[k8][0], qf[k8][1], qf[k8][2], qf[k8][3], b0, b1);
            }
        }

        if (kt == qi) {
            int r0l = wr + g, r1l = r0l + 8;
            #pragma unroll
            for (int nt = 0; nt < 8; ++nt) {
                int c = nt * 8 + 2 * t;
                if (c > r0l)     s[nt][0] = -CUDART_INF_F;
                if (c + 1 > r0l) s[nt][1] = -CUDART_INF_F;
                if (c > r1l)     s[nt][2] = -CUDART_INF_F;
                if (c + 1 > r1l) s[nt][3] = -CUDART_INF_F;
            }
        }

        // ---- online softmax (row quads: lanes sharing g) ----
        float rm0 = s[0][0], rm1 = s[0][2];
        #pragma unroll
        for (int nt = 0; nt < 8; ++nt) {
            rm0 = fmaxf(rm0, fmaxf(s[nt][0], s[nt][1]));
            rm1 = fmaxf(rm1, fmaxf(s[nt][2], s[nt][3]));
        }
        rm0 = fmaxf(rm0, __shfl_xor_sync(0xffffffffu, rm0, 1));
        rm0 = fmaxf(rm0, __shfl_xor_sync(0xffffffffu, rm0, 2));
        rm1 = fmaxf(rm1, __shfl_xor_sync(0xffffffffu, rm1, 1));
        rm1 = fmaxf(rm1, __shfl_xor_sync(0xffffffffu, rm1, 2));

        float mn0 = fmaxf(m0, rm0), mn1 = fmaxf(m1, rm1);
        float corr0 = __expf(m0 - mn0), corr1 = __expf(m1 - mn1);
        float rs0 = 0.f, rs1 = 0.f;
        #pragma unroll
        for (int nt = 0; nt < 8; ++nt) {
            s[nt][0] = __expf(s[nt][0] - mn0);
            s[nt][1] = __expf(s[nt][1] - mn0);
            s[nt][2] = __expf(s[nt][2] - mn1);
            s[nt][3] = __expf(s[nt][3] - mn1);
            rs0 += s[nt][0] + s[nt][1];
            rs1 += s[nt][2] + s[nt][3];
        }
        rs0 += __shfl_xor_sync(0xffffffffu, rs0, 1);
        rs0 += __shfl_xor_sync(0xffffffffu, rs0, 2);
        rs1 += __shfl_xor_sync(0xffffffffu, rs1, 1);
        rs1 += __shfl_xor_sync(0xffffffffu, rs1, 2);
        l0 = l0 * corr0 + rs0;  m0 = mn0;
        l1 = l1 * corr1 + rs1;  m1 = mn1;

        #pragma unroll
        for (int nt = 0; nt < 8; ++nt) {
            o[nt][0] *= corr0; o[nt][1] *= corr0;
            o[nt][2] *= corr1; o[nt][3] *= corr1;
        }

        // ---- P -> smem (per-warp-private rows) ----
        #pragma unroll
        for (int nt = 0; nt < 8; ++nt) {
            *(float2*)&Ps[(wr + g) * PS_ST + nt * 8 + 2 * t] =
                make_float2(s[nt][0], s[nt][1]);
            *(float2*)&Ps[(wr + g + 8) * PS_ST + nt * 8 + 2 * t] =
                make_float2(s[nt][2], s[nt][3]);
        }
        __syncwarp();

        // ---- O += P @ V ----
        #pragma unroll
        for (int k8 = 0; k8 < 8; ++k8) {
            const float* pa = Ps + (wr + g) * PS_ST + k8 * 8 + t;
            uint32_t a0 = __float_as_uint(pa[0]);
            uint32_t a1 = __float_as_uint(pa[8 * PS_ST]);
            uint32_t a2 = __float_as_uint(pa[4]);
            uint32_t a3 = __float_as_uint(pa[8 * PS_ST + 4]);
            const float* pv = Vs + (k8 * 8 + t) * VS_ST + g;
            #pragma unroll
            for (int nt = 0; nt < 8; ++nt) {
                uint32_t b0 = __float_as_uint(pv[nt * 8]);
                uint32_t b1 = __float_as_uint(pv[4 * VS_ST + nt * 8]);
                mma_tf32(o[nt][0], o[nt][1], o[nt][2], o[nt][3],
                         a0, a1, a2, a3, b0, b1);
            }
        }
        __syncthreads();   // protect current stage before it is overwritten
    }

    // ---- epilogue: normalize, tf32-round, store [b, s, h*dk] ----
    const int b = bh >> 4;
    const int h = bh & 15;
    const float inv0 = 1.0f / l0, inv1 = 1.0f / l1;
    const int r0g = q0 + wr + g, r1g = r0g + 8;
    #pragma unroll
    for (int nt = 0; nt < 8; ++nt) {
        int col = nt * 8 + 2 * t;
        *(float2*)&Og[((size_t)(b * SS + r0g)) * DD + h * 64 + col] =
            make_float2(tf32_round(o[nt][0] * inv0), tf32_round(o[nt][1] * inv0));
        *(float2*)&Og[((size_t)(b * SS + r1g)) * DD + h * 64 + col] =
            make_float2(tf32_round(o[nt][2] * inv1), tf32_round(o[nt][3] * inv1));
    }
}

// ---------------------------------------------------------------------------

extern "C" void kernel_launch(void* const* d_in, const int* in_sizes, int n_in,
                              void* d_out, int out_size)
{
    const float* x  = (const float*)d_in[0];
    const float* Wq = (const float*)d_in[1];
    const float* bq = (const float*)d_in[2];
    const float* Wk = (const float*)d_in[3];
    const float* bk = (const float*)d_in[4];
    const float* Wv = (const float*)d_in[5];
    const float* bv = (const float*)d_in[6];
    const float* Wo = (const float*)d_in[7];
    const float* bo = (const float*)d_in[8];
    const int*   pos = (const int*)d_in[9];
    float* out = (float*)d_out;

    float *qp, *kp, *vp, *ap, *xt, *wt;
    float2* ropep;
    cudaGetSymbolAddress((void**)&qp, g_q);
    cudaGetSymbolAddress((void**)&kp, g_k);
    cudaGetSymbolAddress((void**)&vp, g_v);
    cudaGetSymbolAddress((void**)&ap, g_attn);
    cudaGetSymbolAddress((void**)&xt, g_xt);
    cudaGetSymbolAddress((void**)&wt, g_wt);
    cudaGetSymbolAddress((void**)&ropep, g_rope);
    float* wto = wt + 3 * (size_t)DD * DD;

    cvt_all_kernel<<<(MM * DD + 4 * DD * DD) / 1024, 256>>>(
        (const float4*)x, (const float4*)Wq, (const float4*)Wk,
        (const float4*)Wv, (const float4*)Wo, (float4*)xt, (float4*)wt);
    rope_table_kernel<<<(MM * 32) / 256, 256>>>(pos, ropep);

    cudaFuncSetAttribute(gemm_tc_kernel,
                         cudaFuncAttributeMaxDynamicSharedMemorySize, GEMM_SMEM);

    // fused QKV projection: W = [Wq|Wk|Wv] (3072 x 1024)
    gemm_tc_kernel<<<dim3(3 * DD / 128, MM / 128), 128, GEMM_SMEM>>>(
        xt, wt, bq, bk, bv, ropep, qp, kp, vp, 1);

    cudaFuncSetAttribute(flash_tc_kernel,
                         cudaFuncAttributeMaxDynamicSharedMemorySize, FLASH_SMEM);
    flash_tc_kernel<<<dim3(SS / 64, BB * HH), 128, FLASH_SMEM>>>(qp, kp, vp, ap);

    // output projection (final output, no rounding)
    gemm_tc_kernel<<<dim3(DD / 128, MM / 128), 128, GEMM_SMEM>>>(
        ap, wto, bo, bo, bo, ropep, out, out, out, 0);
}

// round 6
// speedup vs baseline: 3.1510x; 1.0128x over previous
#include <cuda_runtime.h>
#include <math_constants.h>
#include <cstdint>

// Problem constants (fixed by setup_inputs)
#define BB 2
#define SS 2048
#define HH 16
#define DKK 64
#define DD 1024
#define MM (BB*SS)   // 4096

// Scratch (allocation-free rule: __device__ globals)
__device__ float g_q[(size_t)MM * DD];
__device__ float g_k[(size_t)MM * DD];
__device__ float g_v[(size_t)MM * DD];
__device__ float g_attn[(size_t)MM * DD];
__device__ float g_xt[(size_t)MM * DD];          // tf32-rounded x
__device__ float g_wt[4 * (size_t)DD * DD];      // tf32-rounded Wq,Wk,Wv,Wo (contiguous)
__device__ float2 g_rope[(size_t)MM * 32];       // (cos, sin) per (row, freq)

__device__ __forceinline__ float tf32_round(float x) {
    unsigned u;
    asm("cvt.rna.tf32.f32 %0, %1;" : "=r"(u) : "f"(x));
    return __uint_as_float(u);
}

__device__ __forceinline__ void mma_tf32(
    float& d0, float& d1, float& d2, float& d3,
    uint32_t a0, uint32_t a1, uint32_t a2, uint32_t a3,
    uint32_t b0, uint32_t b1)
{
    asm volatile(
        "mma.sync.aligned.m16n8k8.row.col.f32.tf32.tf32.f32 "
        "{%0,%1,%2,%3}, {%4,%5,%6,%7}, {%8,%9}, {%0,%1,%2,%3};\n"
        : "+f"(d0), "+f"(d1), "+f"(d2), "+f"(d3)
        : "r"(a0), "r"(a1), "r"(a2), "r"(a3), "r"(b0), "r"(b1));
}

__device__ __forceinline__ void cp_async16(uint32_t dst, const void* src) {
    asm volatile("cp.async.cg.shared.global [%0], [%1], 16;\n" :: "r"(dst), "l"(src));
}

// ---------------------------------------------------------------------------
// Merged tf32 rounding prepass: x + 4 weights into g_xt / g_wt.
// ---------------------------------------------------------------------------
__global__ __launch_bounds__(256) void cvt_all_kernel(
    const float4* __restrict__ x,
    const float4* __restrict__ wq, const float4* __restrict__ wk,
    const float4* __restrict__ wv, const float4* __restrict__ wo,
    float4* __restrict__ xt, float4* __restrict__ wt)
{
    const int NX = MM * DD / 4;      // 1048576
    const int NW = DD * DD / 4;      // 262144
    int i = blockIdx.x * 256 + threadIdx.x;
    const float4* src;
    float4* dst;
    int off;
    if (i < NX) { src = x; dst = xt; off = i; }
    else {
        int j = i - NX;
        int w = j >> 18;
        off = j & (NW - 1);
        src = (w == 0) ? wq : (w == 1) ? wk : (w == 2) ? wv : wo;
        dst = wt + (size_t)w * NW;
    }
    float4 v = src[off];
    v.x = tf32_round(v.x); v.y = tf32_round(v.y);
    v.z = tf32_round(v.z); v.w = tf32_round(v.w);
    dst[off] = v;
}

// ---------------------------------------------------------------------------
// RoPE table: rope[m][f] = (cos, sin) of pos[m] * theta^(-2f/64).
// ---------------------------------------------------------------------------
__global__ __launch_bounds__(256) void rope_table_kernel(
    const int* __restrict__ pos, float2* __restrict__ rope)
{
    int i = blockIdx.x * 256 + threadIdx.x;   // 0 .. MM*32-1
    int m = i >> 5, f = i & 31;
    const float KF = 0.14391157f;             // ln(10000)/64
    float invf = expf(-2.0f * (float)f * KF);
    float a = (float)pos[m] * invf;
    float sn, cs;
    sincosf(a, &sn, &cs);
    rope[i] = make_float2(cs, sn);
}

// ---------------------------------------------------------------------------
// tf32 mma GEMM: C[M,N] = A[M,K] @ W[N,K]^T + bias.   (unchanged from R5)
// ---------------------------------------------------------------------------
#define GSA 4608               // floats per matrix per stage (128*36)
#define GSTG 9216              // floats per stage (A+B)
#define GNSTG 3
#define GEMM_SMEM (GNSTG * GSTG * 4)   // 110592 B
#define GNC (DD / 32)          // 32 k-chunks

__global__ __launch_bounds__(128) void gemm_tc_kernel(
    const float* __restrict__ A, const float* __restrict__ W,
    const float* __restrict__ bQ, const float* __restrict__ bK,
    const float* __restrict__ bV,
    const float2* __restrict__ rope,
    float* __restrict__ oQ, float* __restrict__ oK, float* __restrict__ oV,
    int mode)
{
    extern __shared__ float smem[];
    const uint32_t smem_u = (uint32_t)__cvta_generic_to_shared(smem);

    const int tid = threadIdx.x;
    const int lane = tid & 31;
    const int wid = tid >> 5;
    const int g = lane >> 2;
    const int t = lane & 3;
    const int wm0 = (wid >> 1) * 64;
    const int wn0 = (wid & 1) * 64;
    const int m0 = blockIdx.y * 128;
    const int n0 = blockIdx.x * 128;

    const int seg = tid & 7;
    const int rbase = tid >> 3;
    const float* aoff = A + (size_t)(m0 + rbase) * DD + seg * 4;
    const float* boff = W + (size_t)(n0 + rbase) * DD + seg * 4;
    const uint32_t sdst = (uint32_t)((rbase * 36 + seg * 4) * 4);

    float d[4][8][4];
    #pragma unroll
    for (int mt = 0; mt < 4; ++mt)
        #pragma unroll
        for (int nt = 0; nt < 8; ++nt)
            #pragma unroll
            for (int e = 0; e < 4; ++e) d[mt][nt][e] = 0.f;

    #pragma unroll
    for (int p = 0; p < 2; ++p) {
        uint32_t sb = smem_u + p * GSTG * 4 + sdst;
        #pragma unroll
        for (int j = 0; j < 8; ++j) {
            cp_async16(sb + j * (16 * 36 * 4), aoff + (size_t)j * 16 * DD + p * 32);
            cp_async16(sb + GSA * 4 + j * (16 * 36 * 4), boff + (size_t)j * 16 * DD + p * 32);
        }
        asm volatile("cp.async.commit_group;" ::: "memory");
    }

    int stg = 2;
    for (int kc = 0; kc < GNC; ++kc) {
        if (kc + 2 < GNC) {
            uint32_t sb = smem_u + stg * GSTG * 4 + sdst;
            const int ko = (kc + 2) * 32;
            #pragma unroll
            for (int j = 0; j < 8; ++j) {
                cp_async16(sb + j * (16 * 36 * 4), aoff + (size_t)j * 16 * DD + ko);
                cp_async16(sb + GSA * 4 + j * (16 * 36 * 4), boff + (size_t)j * 16 * DD + ko);
            }
        }
        asm volatile("cp.async.commit_group;" ::: "memory");
        asm volatile("cp.async.wait_group 2;" ::: "memory");
        __syncthreads();

        const int cur = (stg + 1 == GNSTG) ? 0 : stg + 1;
        const float* Sa = smem + cur * GSTG;
        const float* Sb = Sa + GSA;

        #pragma unroll
        for (int k8 = 0; k8 < 32; k8 += 8) {
            uint32_t a[4][4], b[8][2];
            #pragma unroll
            for (int mt = 0; mt < 4; ++mt) {
                const float* pa = Sa + (wm0 + mt * 16 + g) * 36 + k8 + t;
                a[mt][0] = __float_as_uint(pa[0]);
                a[mt][1] = __float_as_uint(pa[8 * 36]);
                a[mt][2] = __float_as_uint(pa[4]);
                a[mt][3] = __float_as_uint(pa[8 * 36 + 4]);
            }
            #pragma unroll
            for (int nt = 0; nt < 8; ++nt) {
                const float* pb = Sb + (wn0 + nt * 8 + g) * 36 + k8 + t;
                b[nt][0] = __float_as_uint(pb[0]);
                b[nt][1] = __float_as_uint(pb[4]);
            }
            #pragma unroll
            for (int mt = 0; mt < 4; ++mt)
                #pragma unroll
                for (int nt = 0; nt < 8; ++nt)
                    mma_tf32(d[mt][nt][0], d[mt][nt][1], d[mt][nt][2], d[mt][nt][3],
                             a[mt][0], a[mt][1], a[mt][2], a[mt][3],
                             b[nt][0], b[nt][1]);
        }
        __syncthreads();
        stg = cur;
    }

    #pragma unroll
    for (int mt = 0; mt < 4; ++mt) {
        int r0 = m0 + wm0 + mt * 16 + g;
        int r1 = r0 + 8;
        const float2* rp0 = rope + (size_t)r0 * 32;
        const float2* rp1 = rope + (size_t)r1 * 32;
        #pragma unroll
        for (int nt = 0; nt < 8; ++nt) {
            int c = n0 + wn0 + nt * 8 + 2 * t;
            if (mode == 0) {
                float bv0 = __ldg(bQ + c), bv1 = __ldg(bQ + c + 1);
                *(float2*)&oQ[(size_t)r0 * DD + c] =
                    make_float2(d[mt][nt][0] + bv0, d[mt][nt][1] + bv1);
                *(float2*)&oQ[(size_t)r1 * DD + c] =
                    make_float2(d[mt][nt][2] + bv0, d[mt][nt][3] + bv1);
            } else {
                const int which = c >> 10;
                const int cc = c & 1023;
                const int h = cc >> 6, cl = cc & 63;
                const float* bp = (which == 0) ? bQ : (which == 1) ? bK : bV;
                float* outp = (which == 0) ? oQ : (which == 1) ? oK : oV;
                float bv0 = __ldg(bp + cc), bv1 = __ldg(bp + cc + 1);
                float v00 = d[mt][nt][0] + bv0, v01 = d[mt][nt][1] + bv1;
                float v10 = d[mt][nt][2] + bv0, v11 = d[mt][nt][3] + bv1;
                if (which < 2) {
                    float2 cs0 = rp0[cl >> 1], cs1 = rp1[cl >> 1];
                    float e, od;
                    e  = v00 * cs0.x - v01 * cs0.y;
                    od = v00 * cs0.y + v01 * cs0.x;  v00 = e; v01 = od;
                    e  = v10 * cs1.x - v11 * cs1.y;
                    od = v10 * cs1.y + v11 * cs1.x;  v10 = e; v11 = od;
                }
                int b0i = r0 >> 11, s0 = r0 & (SS - 1);
                int b1i = r1 >> 11, s1 = r1 & (SS - 1);
                *(float2*)&outp[(((size_t)(b0i * HH + h) * SS + s0) * DKK) + cl] =
                    make_float2(tf32_round(v00), tf32_round(v01));
                *(float2*)&outp[(((size_t)(b1i * HH + h) * SS + s1) * DKK) + cl] =
                    make_float2(tf32_round(v10), tf32_round(v11));
            }
        }
    }
}

// ---------------------------------------------------------------------------
// Tensor-core flash attention (tf32 mma, fp32 softmax, causal).
// Br=128 (256 threads = 8 warps x 16 rows), Bc=64, KV double-buffered.
// 2 CTAs/SM (104KB smem, <=128 regs) -> 16 warps/SM.
// Per-warp tile skipping above the diagonal.
// ---------------------------------------------------------------------------
#define KS_ST 68
#define VS_ST 72
#define PS_ST 68
#define FK_STG (64*KS_ST + 64*VS_ST)                   // 8960 floats / stage
#define FLASH_SMEM ((2*FK_STG + 128*PS_ST) * 4)        // 106496 B

__global__ __launch_bounds__(256, 2) void flash_tc_kernel(
    const float* __restrict__ Qg, const float* __restrict__ Kg,
    const float* __restrict__ Vg, float* __restrict__ Og)
{
    extern __shared__ float sm[];
    float* Ps = sm + 2 * FK_STG;      // [128][68]: Q staging, then P
    const uint32_t smem_u = (uint32_t)__cvta_generic_to_shared(sm);

    const int qi = (int)(gridDim.x - 1) - (int)blockIdx.x;  // big tiles first
    const int bh = blockIdx.y;
    const int q0 = qi * 128;
    const float* Qb = Qg + (size_t)bh * SS * DKK;
    const float* Kb = Kg + (size_t)bh * SS * DKK;
    const float* Vb = Vg + (size_t)bh * SS * DKK;

    const int tid = threadIdx.x;
    const int lane = tid & 31;
    const int wid = tid >> 5;
    const int g = lane >> 2;
    const int t = lane & 3;
    const int wr = wid * 16;          // warp row base (0..112)

    // loader decomposition: kv tile = 64 rows x 16 seg(16B); 4 per tensor/thread
    const int fr = tid >> 4;          // 0..15, rows fr + 16j (j<4)
    const int fc = tid & 15;
    const float* ksrc = Kb + (size_t)fr * DKK + fc * 4;
    const float* vsrc = Vb + (size_t)fr * DKK + fc * 4;
    const uint32_t kdst = smem_u + (uint32_t)(fr * (KS_ST*4) + fc * 16);
    const uint32_t vdst = smem_u + (uint32_t)(64*KS_ST*4 + fr * (VS_ST*4) + fc * 16);

    // ---- stage Q (scaled by 1/8, RNA tf32) into Ps ----
    #pragma unroll
    for (int l = 0; l < 8; ++l) {
        int idx = tid + l * 256;      // 0..2047 float4 units (128 rows x 16)
        int row = idx >> 4;
        int c4 = (idx & 15) << 2;
        float4 q = *(const float4*)&Qb[(size_t)(q0 + row) * DKK + c4];
        q.x = tf32_round(q.x * 0.125f);
        q.y = tf32_round(q.y * 0.125f);
        q.z = tf32_round(q.z * 0.125f);
        q.w = tf32_round(q.w * 0.125f);
        *(float4*)&Ps[row * PS_ST + c4] = q;
    }

    // prologue: KV tile 0 -> stage 0
    #pragma unroll
    for (int j = 0; j < 4; ++j) {
        cp_async16(kdst + j * (16 * KS_ST * 4), ksrc + (size_t)j * 16 * DKK);
        cp_async16(vdst + j * (16 * VS_ST * 4), vsrc + (size_t)j * 16 * DKK);
    }
    asm volatile("cp.async.commit_group;" ::: "memory");

    __syncthreads();
    uint32_t qf[8][4];
    #pragma unroll
    for (int k8 = 0; k8 < 8; ++k8) {
        const float* pa = Ps + (wr + g) * PS_ST + k8 * 8 + t;
        qf[k8][0] = __float_as_uint(pa[0]);
        qf[k8][1] = __float_as_uint(pa[8 * PS_ST]);
        qf[k8][2] = __float_as_uint(pa[4]);
        qf[k8][3] = __float_as_uint(pa[8 * PS_ST + 4]);
    }
    __syncthreads();  // Ps free for P use

    float o[8][4];
    #pragma unroll
    for (int nt = 0; nt < 8; ++nt)
        #pragma unroll
        for (int e = 0; e < 4; ++e) o[nt][e] = 0.f;
    float m0 = -CUDART_INF_F, m1 = -CUDART_INF_F;
    float l0 = 0.f, l1 = 0.f;

    const int rmax = q0 + wr + 15;          // last row this warp owns
    const int ktend = 2 * qi + 2;           // kv tiles covering rows < q0+128

    for (int kt = 0; kt < ktend; ++kt) {
        const int k0 = kt * 64;
        // prefetch next KV tile into the other stage
        if (kt + 1 < ktend) {
            uint32_t so = (uint32_t)(((kt + 1) & 1) * FK_STG * 4);
            const size_t go = (size_t)(kt + 1) * 64 * DKK;
            #pragma unroll
            for (int j = 0; j < 4; ++j) {
                cp_async16(kdst + so + j * (16 * KS_ST * 4), ksrc + go + (size_t)j * 16 * DKK);
                cp_async16(vdst + so + j * (16 * VS_ST * 4), vsrc + go + (size_t)j * 16 * DKK);
            }
        }
        asm volatile("cp.async.commit_group;" ::: "memory");
        asm volatile("cp.async.wait_group 1;" ::: "memory");   // tile kt ready
        __syncthreads();

        if (k0 <= rmax) {   // warp has at least one unmasked row in this tile
            const float* Ks = sm + (kt & 1) * FK_STG;
            const float* Vs = Ks + 64 * KS_ST;

            // ---- S = Q @ K^T ----
            float s[8][4];
            #pragma unroll
            for (int nt = 0; nt < 8; ++nt)
                #pragma unroll
                for (int e = 0; e < 4; ++e) s[nt][e] = 0.f;

            #pragma unroll
            for (int k8 = 0; k8 < 8; ++k8) {
                const float* pk = Ks + g * KS_ST + k8 * 8 + t;
                #pragma unroll
                for (int nt = 0; nt < 8; ++nt) {
                    uint32_t b0 = __float_as_uint(pk[nt * 8 * KS_ST]);
                    uint32_t b1 = __float_as_uint(pk[nt * 8 * KS_ST + 4]);
                    mma_tf32(s[nt][0], s[nt][1], s[nt][2], s[nt][3],
                             qf[k8][0], qf[k8][1], qf[k8][2], qf[k8][3], b0, b1);
                }
            }

            // ---- causal mask if tile crosses this warp's diagonal ----
            if (k0 + 63 > q0 + wr) {
                int r0l = q0 + wr + g, r1l = r0l + 8;
                #pragma unroll
                for (int nt = 0; nt < 8; ++nt) {
                    int c = k0 + nt * 8 + 2 * t;
                    if (c > r0l)     s[nt][0] = -CUDART_INF_F;
                    if (c + 1 > r0l) s[nt][1] = -CUDART_INF_F;
                    if (c > r1l)     s[nt][2] = -CUDART_INF_F;
                    if (c + 1 > r1l) s[nt][3] = -CUDART_INF_F;
                }
            }

            // ---- online softmax (row quads) ----
            float rm0 = s[0][0], rm1 = s[0][2];
            #pragma unroll
            for (int nt = 0; nt < 8; ++nt) {
                rm0 = fmaxf(rm0, fmaxf(s[nt][0], s[nt][1]));
                rm1 = fmaxf(rm1, fmaxf(s[nt][2], s[nt][3]));
            }
            rm0 = fmaxf(rm0, __shfl_xor_sync(0xffffffffu, rm0, 1));
            rm0 = fmaxf(rm0, __shfl_xor_sync(0xffffffffu, rm0, 2));
            rm1 = fmaxf(rm1, __shfl_xor_sync(0xffffffffu, rm1, 1));
            rm1 = fmaxf(rm1, __shfl_xor_sync(0xffffffffu, rm1, 2));

            float mn0 = fmaxf(m0, rm0), mn1 = fmaxf(m1, rm1);
            float corr0 = __expf(m0 - mn0), corr1 = __expf(m1 - mn1);
            float rs0 = 0.f, rs1 = 0.f;
            #pragma unroll
            for (int nt = 0; nt < 8; ++nt) {
                s[nt][0] = __expf(s[nt][0] - mn0);
                s[nt][1] = __expf(s[nt][1] - mn0);
                s[nt][2] = __expf(s[nt][2] - mn1);
                s[nt][3] = __expf(s[nt][3] - mn1);
                rs0 += s[nt][0] + s[nt][1];
                rs1 += s[nt][2] + s[nt][3];
            }
            rs0 += __shfl_xor_sync(0xffffffffu, rs0, 1);
            rs0 += __shfl_xor_sync(0xffffffffu, rs0, 2);
            rs1 += __shfl_xor_sync(0xffffffffu, rs1, 1);
            rs1 += __shfl_xor_sync(0xffffffffu, rs1, 2);
            l0 = l0 * corr0 + rs0;  m0 = mn0;
            l1 = l1 * corr1 + rs1;  m1 = mn1;

            #pragma unroll
            for (int nt = 0; nt < 8; ++nt) {
                o[nt][0] *= corr0; o[nt][1] *= corr0;
                o[nt][2] *= corr1; o[nt][3] *= corr1;
            }

            // ---- P -> smem (per-warp-private rows) ----
            #pragma unroll
            for (int nt = 0; nt < 8; ++nt) {
                *(float2*)&Ps[(wr + g) * PS_ST + nt * 8 + 2 * t] =
                    make_float2(s[nt][0], s[nt][1]);
                *(float2*)&Ps[(wr + g + 8) * PS_ST + nt * 8 + 2 * t] =
                    make_float2(s[nt][2], s[nt][3]);
            }
            __syncwarp();

            // ---- O += P @ V ----
            #pragma unroll
            for (int k8 = 0; k8 < 8; ++k8) {
                const float* pa = Ps + (wr + g) * PS_ST + k8 * 8 + t;
                uint32_t a0 = __float_as_uint(pa[0]);
                uint32_t a1 = __float_as_uint(pa[8 * PS_ST]);
                uint32_t a2 = __float_as_uint(pa[4]);
                uint32_t a3 = __float_as_uint(pa[8 * PS_ST + 4]);
                const float* pv = Vs + (k8 * 8 + t) * VS_ST + g;
                #pragma unroll
                for (int nt = 0; nt < 8; ++nt) {
                    uint32_t b0 = __float_as_uint(pv[nt * 8]);
                    uint32_t b1 = __float_as_uint(pv[4 * VS_ST + nt * 8]);
                    mma_tf32(o[nt][0], o[nt][1], o[nt][2], o[nt][3],
                             a0, a1, a2, a3, b0, b1);
                }
            }
        }
        __syncthreads();   // protect current stage before it is overwritten
    }

    // ---- epilogue: normalize, tf32-round, store [b, s, h*dk] ----
    const int b = bh >> 4;
    const int h = bh & 15;
    const float inv0 = 1.0f / l0, inv1 = 1.0f / l1;
    const int r0g = q0 + wr + g, r1g = r0g + 8;
    #pragma unroll
    for (int nt = 0; nt < 8; ++nt) {
        int col = nt * 8 + 2 * t;
        *(float2*)&Og[((size_t)(b * SS + r0g)) * DD + h * 64 + col] =
            make_float2(tf32_round(o[nt][0] * inv0), tf32_round(o[nt][1] * inv0));
        *(float2*)&Og[((size_t)(b * SS + r1g)) * DD + h * 64 + col] =
            make_float2(tf32_round(o[nt][2] * inv1), tf32_round(o[nt][3] * inv1));
    }
}

// ---------------------------------------------------------------------------

extern "C" void kernel_launch(void* const* d_in, const int* in_sizes, int n_in,
                              void* d_out, int out_size)
{
    const float* x  = (const float*)d_in[0];
    const float* Wq = (const float*)d_in[1];
    const float* bq = (const float*)d_in[2];
    const float* Wk = (const float*)d_in[3];
    const float* bk = (const float*)d_in[4];
    const float* Wv = (const float*)d_in[5];
    const float* bv = (const float*)d_in[6];
    const float* Wo = (const float*)d_in[7];
    const float* bo = (const float*)d_in[8];
    const int*   pos = (const int*)d_in[9];
    float* out = (float*)d_out;

    float *qp, *kp, *vp, *ap, *xt, *wt;
    float2* ropep;
    cudaGetSymbolAddress((void**)&qp, g_q);
    cudaGetSymbolAddress((void**)&kp, g_k);
    cudaGetSymbolAddress((void**)&vp, g_v);
    cudaGetSymbolAddress((void**)&ap, g_attn);
    cudaGetSymbolAddress((void**)&xt, g_xt);
    cudaGetSymbolAddress((void**)&wt, g_wt);
    cudaGetSymbolAddress((void**)&ropep, g_rope);
    float* wto = wt + 3 * (size_t)DD * DD;

    cvt_all_kernel<<<(MM * DD + 4 * DD * DD) / 1024, 256>>>(
        (const float4*)x, (const float4*)Wq, (const float4*)Wk,
        (const float4*)Wv, (const float4*)Wo, (float4*)xt, (float4*)wt);
    rope_table_kernel<<<(MM * 32) / 256, 256>>>(pos, ropep);

    cudaFuncSetAttribute(gemm_tc_kernel,
                         cudaFuncAttributeMaxDynamicSharedMemorySize, GEMM_SMEM);

    // fused QKV projection: W = [Wq|Wk|Wv] (3072 x 1024)
    gemm_tc_kernel<<<dim3(3 * DD / 128, MM / 128), 128, GEMM_SMEM>>>(
        xt, wt, bq, bk, bv, ropep, qp, kp, vp, 1);

    cudaFuncSetAttribute(flash_tc_kernel,
                         cudaFuncAttributeMaxDynamicSharedMemorySize, FLASH_SMEM);
    flash_tc_kernel<<<dim3(SS / 128, BB * HH), 256, FLASH_SMEM>>>(qp, kp, vp, ap);

    // output projection (final output, no rounding)
    gemm_tc_kernel<<<dim3(DD / 128, MM / 128), 128, GEMM_SMEM>>>(
        ap, wto, bo, bo, bo, ropep, out, out, out, 0);
}

// round 7
// speedup vs baseline: 5.9728x; 1.8955x over previous
#include <cuda_runtime.h>
#include <cuda_fp16.h>
#include <math_constants.h>
#include <cstdint>

// Problem constants (fixed by setup_inputs)
#define BB 2
#define SS 2048
#define HH 16
#define DKK 64
#define DD 1024
#define MM (BB*SS)   // 4096

// Scratch (allocation-free rule: __device__ globals)
__device__ __half g_xh[(size_t)MM * DD];         // fp16 x
__device__ __half g_wh[4 * (size_t)DD * DD];     // fp16 Wq,Wk,Wv,Wo (contiguous)
__device__ __half g_qh[(size_t)MM * DD];         // Q (pre-scaled by 1/8, RoPE'd)
__device__ __half g_kh[(size_t)MM * DD];
__device__ __half g_vh[(size_t)MM * DD];
__device__ __half g_ah[(size_t)MM * DD];         // attention output
__device__ float2 g_rope[(size_t)MM * 32];       // (cos, sin) per (row, freq)

__device__ __forceinline__ void mma_f16(
    float& d0, float& d1, float& d2, float& d3,
    uint32_t a0, uint32_t a1, uint32_t a2, uint32_t a3,
    uint32_t b0, uint32_t b1)
{
    asm volatile(
        "mma.sync.aligned.m16n8k16.row.col.f32.f16.f16.f32 "
        "{%0,%1,%2,%3}, {%4,%5,%6,%7}, {%8,%9}, {%0,%1,%2,%3};\n"
        : "+f"(d0), "+f"(d1), "+f"(d2), "+f"(d3)
        : "r"(a0), "r"(a1), "r"(a2), "r"(a3), "r"(b0), "r"(b1));
}

#define LDSM_X4(r0,r1,r2,r3,addr) \
    asm volatile("ldmatrix.sync.aligned.m8n8.x4.shared.b16 {%0,%1,%2,%3}, [%4];" \
        : "=r"(r0), "=r"(r1), "=r"(r2), "=r"(r3) : "r"(addr))

#define LDSM_X4_T(r0,r1,r2,r3,addr) \
    asm volatile("ldmatrix.sync.aligned.m8n8.x4.trans.shared.b16 {%0,%1,%2,%3}, [%4];" \
        : "=r"(r0), "=r"(r1), "=r"(r2), "=r"(r3) : "r"(addr))

__device__ __forceinline__ void cp_async16(uint32_t dst, const void* src) {
    asm volatile("cp.async.cg.shared.global [%0], [%1], 16;\n" :: "r"(dst), "l"(src));
}

__device__ __forceinline__ uint32_t pack_h2(float lo, float hi) {
    __half2 h = __float22half2_rn(make_float2(lo, hi));
    return *(uint32_t*)&h;
}

// ---------------------------------------------------------------------------
// fp16 conversion prepass: x + 4 weights. Unit = 8 floats -> 8 halves.
// ---------------------------------------------------------------------------
__global__ __launch_bounds__(256) void cvt_h_kernel(
    const float4* __restrict__ x,
    const float4* __restrict__ wq, const float4* __restrict__ wk,
    const float4* __restrict__ wv, const float4* __restrict__ wo,
    __half* __restrict__ xh, __half* __restrict__ wh)
{
    const int NX8 = MM * DD / 8;     // 524288
    const int NW8 = DD * DD / 8;     // 131072
    int i = blockIdx.x * 256 + threadIdx.x;
    const float4* src;
    __half* dst;
    int off;
    if (i < NX8) { src = x; dst = xh; off = i; }
    else {
        int j = i - NX8;
        int w = j / NW8;
        off = j - w * NW8;
        src = (w == 0) ? wq : (w == 1) ? wk : (w == 2) ? wv : wo;
        dst = wh + (size_t)w * (DD * DD);
    }
    float4 f0 = src[2 * off];
    float4 f1 = src[2 * off + 1];
    uint32_t h[4];
    h[0] = pack_h2(f0.x, f0.y);
    h[1] = pack_h2(f0.z, f0.w);
    h[2] = pack_h2(f1.x, f1.y);
    h[3] = pack_h2(f1.z, f1.w);
    *(uint4*)&dst[(size_t)off * 8] = make_uint4(h[0], h[1], h[2], h[3]);
}

// ---------------------------------------------------------------------------
// RoPE table: rope[m][f] = (cos, sin) of pos[m] * theta^(-2f/64).
// ---------------------------------------------------------------------------
__global__ __launch_bounds__(256) void rope_table_kernel(
    const int* __restrict__ pos, float2* __restrict__ rope)
{
    int i = blockIdx.x * 256 + threadIdx.x;   // 0 .. MM*32-1
    int m = i >> 5, f = i & 31;
    const float KF = 0.14391157f;             // ln(10000)/64
    float invf = expf(-2.0f * (float)f * KF);
    float a = (float)pos[m] * invf;
    float sn, cs;
    sincosf(a, &sn, &cs);
    rope[i] = make_float2(cs, sn);
}

// ---------------------------------------------------------------------------
// fp16 mma GEMM: C[M,N] = A[M,K] @ W[N,K]^T + bias (f32 accumulate).
// CTA tile 128x128, 4 warps of 64x64, k-chunk 32 halves, 3-stage cp.async.
// smem rows padded to 40 halves (80B) -> LDSM conflict-free.
// mode 1: fused QKV (N=3072): [b,h,s,dk] fp16; RoPE on Q,K; Q scaled 1/8.
// mode 0: Wo: float out[m*DD+n].
// ---------------------------------------------------------------------------
#define GROWB 80                    // bytes per smem row (40 halves)
#define G_A_BYTES (128 * GROWB)     // 10240
#define GSTG_B (2 * G_A_BYTES)      // 20480 per stage (A+B)
#define GNSTG 3
#define GEMM_SMEM (GNSTG * GSTG_B)  // 61440
#define GNC (DD / 32)               // 32 chunks

__global__ __launch_bounds__(128, 2) void gemm_h_kernel(
    const __half* __restrict__ A, const __half* __restrict__ W,
    const float* __restrict__ bQ, const float* __restrict__ bK,
    const float* __restrict__ bV,
    const float2* __restrict__ rope,
    __half* __restrict__ oQ, __half* __restrict__ oK, __half* __restrict__ oV,
    float* __restrict__ outF, int mode)
{
    extern __shared__ char smc[];
    const uint32_t smem_u = (uint32_t)__cvta_generic_to_shared(smc);

    const int tid = threadIdx.x;
    const int lane = tid & 31;
    const int wid = tid >> 5;
    const int g = lane >> 2;
    const int t = lane & 3;
    const int wm0 = (wid >> 1) * 64;
    const int wn0 = (wid & 1) * 64;
    const int m0 = blockIdx.y * 128;
    const int n0 = blockIdx.x * 128;

    // loader: chunk = 128 rows x 4 segs(16B) per matrix; 4 A + 4 B per thread
    const int seg = tid & 3;
    const int rbase = tid >> 2;               // 0..31; rows rbase + 32j
    const __half* aoff = A + (size_t)(m0 + rbase) * DD + seg * 8;
    const __half* boff = W + (size_t)(n0 + rbase) * DD + seg * 8;
    const uint32_t sdst = (uint32_t)(rbase * GROWB + seg * 16);

    float d[4][8][4];
    #pragma unroll
    for (int mt = 0; mt < 4; ++mt)
        #pragma unroll
        for (int nt = 0; nt < 8; ++nt)
            #pragma unroll
            for (int e = 0; e < 4; ++e) d[mt][nt][e] = 0.f;

    #pragma unroll
    for (int p = 0; p < 2; ++p) {
        uint32_t sb = smem_u + p * GSTG_B + sdst;
        #pragma unroll
        for (int j = 0; j < 4; ++j) {
            cp_async16(sb + j * (32 * GROWB), aoff + (size_t)j * 32 * DD + p * 32);
            cp_async16(sb + G_A_BYTES + j * (32 * GROWB), boff + (size_t)j * 32 * DD + p * 32);
        }
        asm volatile("cp.async.commit_group;" ::: "memory");
    }

    // ldmatrix lane addressing (within-tile byte offsets)
    const uint32_t a_lrow = (uint32_t)((lane & 15) * GROWB + ((lane >> 4) << 4));
    const uint32_t b_lrow = (uint32_t)(((lane & 7) + ((lane >> 4) << 3)) * GROWB
                                       + (((lane >> 3) & 1) << 4));

    int stg = 2;
    for (int kc = 0; kc < GNC; ++kc) {
        if (kc + 2 < GNC) {
            uint32_t sb = smem_u + stg * GSTG_B + sdst;
            const int ko = (kc + 2) * 32;
            #pragma unroll
            for (int j = 0; j < 4; ++j) {
                cp_async16(sb + j * (32 * GROWB), aoff + (size_t)j * 32 * DD + ko);
                cp_async16(sb + G_A_BYTES + j * (32 * GROWB), boff + (size_t)j * 32 * DD + ko);
            }
        }
        asm volatile("cp.async.commit_group;" ::: "memory");
        asm volatile("cp.async.wait_group 2;" ::: "memory");
        __syncthreads();

        const int cur = (stg + 1 == GNSTG) ? 0 : stg + 1;
        const uint32_t Sa = smem_u + cur * GSTG_B;
        const uint32_t Sb = Sa + G_A_BYTES;

        #pragma unroll
        for (int ks = 0; ks < 2; ++ks) {
            uint32_t a[4][4], b[4][4];
            #pragma unroll
            for (int mt = 0; mt < 4; ++mt)
                LDSM_X4(a[mt][0], a[mt][1], a[mt][2], a[mt][3],
                        Sa + (wm0 + mt * 16) * GROWB + a_lrow + ks * 32);
            #pragma unroll
            for (int np = 0; np < 4; ++np)
                LDSM_X4(b[np][0], b[np][1], b[np][2], b[np][3],
                        Sb + (wn0 + np * 16) * GROWB + b_lrow + ks * 32);
            #pragma unroll
            for (int mt = 0; mt < 4; ++mt)
                #pragma unroll
                for (int np = 0; np < 4; ++np) {
                    mma_f16(d[mt][2*np][0], d[mt][2*np][1], d[mt][2*np][2], d[mt][2*np][3],
                            a[mt][0], a[mt][1], a[mt][2], a[mt][3], b[np][0], b[np][1]);
                    mma_f16(d[mt][2*np+1][0], d[mt][2*np+1][1], d[mt][2*np+1][2], d[mt][2*np+1][3],
                            a[mt][0], a[mt][1], a[mt][2], a[mt][3], b[np][2], b[np][3]);
                }
        }
        __syncthreads();
        stg = cur;
    }

    // ---- epilogue ----
    #pragma unroll
    for (int mt = 0; mt < 4; ++mt) {
        int r0 = m0 + wm0 + mt * 16 + g;
        int r1 = r0 + 8;
        const float2* rp0 = rope + (size_t)r0 * 32;
        const float2* rp1 = rope + (size_t)r1 * 32;
        #pragma unroll
        for (int nt = 0; nt < 8; ++nt) {
            int c = n0 + wn0 + nt * 8 + 2 * t;
            if (mode == 0) {
                float bv0 = __ldg(bQ + c), bv1 = __ldg(bQ + c + 1);
                *(float2*)&outF[(size_t)r0 * DD + c] =
                    make_float2(d[mt][nt][0] + bv0, d[mt][nt][1] + bv1);
                *(float2*)&outF[(size_t)r1 * DD + c] =
                    make_float2(d[mt][nt][2] + bv0, d[mt][nt][3] + bv1);
            } else {
                const int which = c >> 10;        // 0=Q 1=K 2=V
                const int cc = c & 1023;
                const int h = cc >> 6, cl = cc & 63;
                const float* bp = (which == 0) ? bQ : (which == 1) ? bK : bV;
                __half* outp = (which == 0) ? oQ : (which == 1) ? oK : oV;
                float bv0 = __ldg(bp + cc), bv1 = __ldg(bp + cc + 1);
                float v00 = d[mt][nt][0] + bv0, v01 = d[mt][nt][1] + bv1;
                float v10 = d[mt][nt][2] + bv0, v11 = d[mt][nt][3] + bv1;
                if (which < 2) {                  // RoPE on Q,K
                    float2 cs0 = rp0[cl >> 1], cs1 = rp1[cl >> 1];
                    float e, od;
                    e  = v00 * cs0.x - v01 * cs0.y;
                    od = v00 * cs0.y + v01 * cs0.x;  v00 = e; v01 = od;
                    e  = v10 * cs1.x - v11 * cs1.y;
                    od = v10 * cs1.y + v11 * cs1.x;  v10 = e; v11 = od;
                }
                float sc = (which == 0) ? 0.125f : 1.0f;   // pre-scale Q by 1/sqrt(dk)
                int b0i = r0 >> 11, s0 = r0 & (SS - 1);
                int b1i = r1 >> 11, s1 = r1 & (SS - 1);
                size_t o0 = (((size_t)(b0i * HH + h) * SS + s0) * DKK) + cl;
                size_t o1 = (((size_t)(b1i * HH + h) * SS + s1) * DKK) + cl;
                *(__half2*)&outp[o0] = __float22half2_rn(make_float2(v00 * sc, v01 * sc));
                *(__half2*)&outp[o1] = __float22half2_rn(make_float2(v10 * sc, v11 * sc));
            }
        }
    }
}

// ---------------------------------------------------------------------------
// fp16 tensor-core flash attention (f32 softmax/accum, causal).
// Br=128 (256 thr = 8 warps x 16 rows), Bc=64, KV double-buffered.
// K: ldmatrix (non-trans, B pattern); V: ldmatrix.trans; P: in-register
// C->A fragment conversion (no smem round-trip). Q pre-scaled by 1/8.
// ---------------------------------------------------------------------------
#define FROWB 144                       // bytes per smem row (72 halves)
#define FTILE_B (64 * FROWB)            // 9216 B per tensor per stage
#define FSTG_B (2 * FTILE_B)            // 18432 B per stage (K+V)
#define FLASH_SMEM (2 * FSTG_B)         // 36864 B

__global__ __launch_bounds__(256, 2) void flash_h_kernel(
    const __half* __restrict__ Qg, const __half* __restrict__ Kg,
    const __half* __restrict__ Vg, __half* __restrict__ Og)
{
    extern __shared__ char smc[];
    __half* smh = (__half*)smc;
    const uint32_t smem_u = (uint32_t)__cvta_generic_to_shared(smc);

    const int qi = (int)(gridDim.x - 1) - (int)blockIdx.x;  // big tiles first
    const int bh = blockIdx.y;
    const int q0 = qi * 128;
    const __half* Qb = Qg + (size_t)bh * SS * DKK;
    const __half* Kb = Kg + (size_t)bh * SS * DKK;
    const __half* Vb = Vg + (size_t)bh * SS * DKK;

    const int tid = threadIdx.x;
    const int lane = tid & 31;
    const int wid = tid >> 5;
    const int g = lane >> 2;
    const int t = lane & 3;
    const int wr = wid * 16;          // warp row base (0..112)

    // ---- stage Q tile (128 x 64 halves, row stride 72) into stage-0 area ----
    #pragma unroll
    for (int j = 0; j < 4; ++j) {
        int u = tid + j * 256;        // 0..1023
        int row = u >> 3;
        int sg = u & 7;
        uint4 v = *(const uint4*)&Qb[(size_t)(q0 + row) * DKK + sg * 8];
        *(uint4*)&smh[row * 72 + sg * 8] = v;
    }
    __syncthreads();

    // Q fragments: A pattern, rows wr..wr+15, 4 k16-steps
    const uint32_t a_lrow = (uint32_t)((lane & 15) * FROWB + ((lane >> 4) << 4));
    uint32_t qf[4][4];
    #pragma unroll
    for (int ks = 0; ks < 4; ++ks)
        LDSM_X4(qf[ks][0], qf[ks][1], qf[ks][2], qf[ks][3],
                smem_u + wr * FROWB + a_lrow + ks * 32);
    __syncthreads();

    // KV loader: 64 rows x 8 segs per tensor; 2 K + 2 V segs per thread
    const int fr = tid >> 3;          // wait: 512 segs/256 thr = 2 each per tensor
    const int fsg = tid & 7;
    const __half* ksrc = Kb + (size_t)fr * DKK + fsg * 8;
    const __half* vsrc = Vb + (size_t)fr * DKK + fsg * 8;
    const uint32_t kdst = smem_u + (uint32_t)(fr * FROWB + fsg * 16);
    const uint32_t vdst = kdst + FTILE_B;

    // prologue: KV tile 0 -> stage 0
    #pragma unroll
    for (int j = 0; j < 2; ++j) {
        cp_async16(kdst + j * (32 * FROWB), ksrc + (size_t)j * 32 * DKK);
        cp_async16(vdst + j * (32 * FROWB), vsrc + (size_t)j * 32 * DKK);
    }
    asm volatile("cp.async.commit_group;" ::: "memory");

    // ldmatrix lane offsets for K (B pattern) and V (trans pattern)
    const uint32_t b_lrow = (uint32_t)(((lane & 7) + ((lane >> 4) << 3)) * FROWB
                                       + (((lane >> 3) & 1) << 4));
    const uint32_t v_lrow = (uint32_t)(((lane & 7) + (((lane >> 3) & 1) << 3)) * FROWB
                                       + ((lane >> 4) << 4));

    float o[8][4];
    #pragma unroll
    for (int nt = 0; nt < 8; ++nt)
        #pragma unroll
        for (int e = 0; e < 4; ++e) o[nt][e] = 0.f;
    float m0 = -CUDART_INF_F, m1 = -CUDART_INF_F;
    float l0 = 0.f, l1 = 0.f;

    const int rmax = q0 + wr + 15;
    const int ktend = 2 * qi + 2;

    for (int kt = 0; kt < ktend; ++kt) {
        const int k0 = kt * 64;
        if (kt + 1 < ktend) {
            uint32_t so = (uint32_t)(((kt + 1) & 1) * FSTG_B);
            const size_t go = (size_t)(kt + 1) * 64 * DKK;
            #pragma unroll
            for (int j = 0; j < 2; ++j) {
                cp_async16(kdst + so + j * (32 * FROWB), ksrc + go + (size_t)j * 32 * DKK);
                cp_async16(vdst + so + j * (32 * FROWB), vsrc + go + (size_t)j * 32 * DKK);
            }
        }
        asm volatile("cp.async.commit_group;" ::: "memory");
        asm volatile("cp.async.wait_group 1;" ::: "memory");
        __syncthreads();

        if (k0 <= rmax) {
            const uint32_t Ks = smem_u + (kt & 1) * FSTG_B;
            const uint32_t Vs = Ks + FTILE_B;

            // ---- S = Q @ K^T ----
            float s[8][4];
            #pragma unroll
            for (int nt = 0; nt < 8; ++nt)
                #pragma unroll
                for (int e = 0; e < 4; ++e) s[nt][e] = 0.f;

            #pragma unroll
            for (int ks = 0; ks < 4; ++ks) {
                uint32_t b[4][4];
                #pragma unroll
                for (int np = 0; np < 4; ++np)
                    LDSM_X4(b[np][0], b[np][1], b[np][2], b[np][3],
                            Ks + (np * 16) * FROWB + b_lrow + ks * 32);
                #pragma unroll
                for (int np = 0; np < 4; ++np) {
                    mma_f16(s[2*np][0], s[2*np][1], s[2*np][2], s[2*np][3],
                            qf[ks][0], qf[ks][1], qf[ks][2], qf[ks][3],
                            b[np][0], b[np][1]);
                    mma_f16(s[2*np+1][0], s[2*np+1][1], s[2*np+1][2], s[2*np+1][3],
                            qf[ks][0], qf[ks][1], qf[ks][2], qf[ks][3],
                            b[np][2], b[np][3]);
                }
            }

            // ---- causal mask ----
            if (k0 + 63 > q0 + wr) {
                int r0l = q0 + wr + g, r1l = r0l + 8;
                #pragma unroll
                for (int nt = 0; nt < 8; ++nt) {
                    int c = k0 + nt * 8 + 2 * t;
                    if (c > r0l)     s[nt][0] = -CUDART_INF_F;
                    if (c + 1 > r0l) s[nt][1] = -CUDART_INF_F;
                    if (c > r1l)     s[nt][2] = -CUDART_INF_F;
                    if (c + 1 > r1l) s[nt][3] = -CUDART_INF_F;
                }
            }

            // ---- online softmax (row quads) ----
            float rm0 = s[0][0], rm1 = s[0][2];
            #pragma unroll
            for (int nt = 0; nt < 8; ++nt) {
                rm0 = fmaxf(rm0, fmaxf(s[nt][0], s[nt][1]));
                rm1 = fmaxf(rm1, fmaxf(s[nt][2], s[nt][3]));
            }
            rm0 = fmaxf(rm0, __shfl_xor_sync(0xffffffffu, rm0, 1));
            rm0 = fmaxf(rm0, __shfl_xor_sync(0xffffffffu, rm0, 2));
            rm1 = fmaxf(rm1, __shfl_xor_sync(0xffffffffu, rm1, 1));
            rm1 = fmaxf(rm1, __shfl_xor_sync(0xffffffffu, rm1, 2));

            float mn0 = fmaxf(m0, rm0), mn1 = fmaxf(m1, rm1);
            float corr0 = __expf(m0 - mn0), corr1 = __expf(m1 - mn1);
            float rs0 = 0.f, rs1 = 0.f;
            #pragma unroll
            for (int nt = 0; nt < 8; ++nt) {
                s[nt][0] = __expf(s[nt][0] - mn0);
                s[nt][1] = __expf(s[nt][1] - mn0);
                s[nt][2] = __expf(s[nt][2] - mn1);
                s[nt][3] = __expf(s[nt][3] - mn1);
                rs0 += s[nt][0] + s[nt][1];
                rs1 += s[nt][2] + s[nt][3];
            }
            rs0 += __shfl_xor_sync(0xffffffffu, rs0, 1);
            rs0 += __shfl_xor_sync(0xffffffffu, rs0, 2);
            rs1 += __shfl_xor_sync(0xffffffffu, rs1, 1);
            rs1 += __shfl_xor_sync(0xffffffffu, rs1, 2);
            l0 = l0 * corr0 + rs0;  m0 = mn0;
            l1 = l1 * corr1 + rs1;  m1 = mn1;

            #pragma unroll
            for (int nt = 0; nt < 8; ++nt) {
                o[nt][0] *= corr0; o[nt][1] *= corr0;
                o[nt][2] *= corr1; o[nt][3] *= corr1;
            }

            // ---- P: in-register C->A fragment conversion (fp16) ----
            uint32_t pa[4][4];
            #pragma unroll
            for (int ks = 0; ks < 4; ++ks) {
                pa[ks][0] = pack_h2(s[2*ks][0],   s[2*ks][1]);     // (g,   2t..)
                pa[ks][1] = pack_h2(s[2*ks][2],   s[2*ks][3]);     // (g+8, 2t..)
                pa[ks][2] = pack_h2(s[2*ks+1][0], s[2*ks+1][1]);   // (g,   2t+8..)
                pa[ks][3] = pack_h2(s[2*ks+1][2], s[2*ks+1][3]);   // (g+8, 2t+8..)
            }

            // ---- O += P @ V  (V via ldmatrix.trans) ----
            #pragma unroll
            for (int ks = 0; ks < 4; ++ks) {
                uint32_t b[4][4];
                #pragma unroll
                for (int np = 0; np < 4; ++np)
                    LDSM_X4_T(b[np][0], b[np][1], b[np][2], b[np][3],
                              Vs + (ks * 16) * FROWB + v_lrow + np * 32);
                #pragma unroll
                for (int np = 0; np < 4; ++np) {
                    mma_f16(o[2*np][0], o[2*np][1], o[2*np][2], o[2*np][3],
                            pa[ks][0], pa[ks][1], pa[ks][2], pa[ks][3],
                            b[np][0], b[np][1]);
                    mma_f16(o[2*np+1][0], o[2*np+1][1], o[2*np+1][2], o[2*np+1][3],
                            pa[ks][0], pa[ks][1], pa[ks][2], pa[ks][3],
                            b[np][2], b[np][3]);
                }
            }
        }
        __syncthreads();   // protect current stage before overwrite
    }

    // ---- epilogue: normalize, store fp16 [b, s, h*dk] ----
    const int b = bh >> 4;
    const int h = bh & 15;
    const float inv0 = 1.0f / l0, inv1 = 1.0f / l1;
    const int r0g = q0 + wr + g, r1g = r0g + 8;
    #pragma unroll
    for (int nt = 0; nt < 8; ++nt) {
        int col = nt * 8 + 2 * t;
        *(__half2*)&Og[((size_t)(b * SS + r0g)) * DD + h * 64 + col] =
            __float22half2_rn(make_float2(o[nt][0] * inv0, o[nt][1] * inv0));
        *(__half2*)&Og[((size_t)(b * SS + r1g)) * DD + h * 64 + col] =
            __float22half2_rn(make_float2(o[nt][2] * inv1, o[nt][3] * inv1));
    }
}

// ---------------------------------------------------------------------------

extern "C" void kernel_launch(void* const* d_in, const int* in_sizes, int n_in,
                              void* d_out, int out_size)
{
    const float* x  = (const float*)d_in[0];
    const float* Wq = (const float*)d_in[1];
    const float* bq = (const float*)d_in[2];
    const float* Wk = (const float*)d_in[3];
    const float* bk = (const float*)d_in[4];
    const float* Wv = (const float*)d_in[5];
    const float* bv = (const float*)d_in[6];
    const float* Wo = (const float*)d_in[7];
    const float* bo = (const float*)d_in[8];
    const int*   pos = (const int*)d_in[9];
    float* out = (float*)d_out;

    __half *xh, *wh, *qh, *kh, *vh, *ah;
    float2* ropep;
    cudaGetSymbolAddress((void**)&xh, g_xh);
    cudaGetSymbolAddress((void**)&wh, g_wh);
    cudaGetSymbolAddress((void**)&qh, g_qh);
    cudaGetSymbolAddress((void**)&kh, g_kh);
    cudaGetSymbolAddress((void**)&vh, g_vh);
    cudaGetSymbolAddress((void**)&ah, g_ah);
    cudaGetSymbolAddress((void**)&ropep, g_rope);
    __half* who = wh + 3 * (size_t)DD * DD;

    cvt_h_kernel<<<(MM * DD / 8 + 4 * DD * DD / 8) / 256, 256>>>(
        (const float4*)x, (const float4*)Wq, (const float4*)Wk,
        (const float4*)Wv, (const float4*)Wo, xh, wh);
    rope_table_kernel<<<(MM * 32) / 256, 256>>>(pos, ropep);

    cudaFuncSetAttribute(gemm_h_kernel,
                         cudaFuncAttributeMaxDynamicSharedMemorySize, GEMM_SMEM);

    // fused QKV projection: W = [Wq|Wk|Wv] (3072 x 1024)
    gemm_h_kernel<<<dim3(3 * DD / 128, MM / 128), 128, GEMM_SMEM>>>(
        xh, wh, bq, bk, bv, ropep, qh, kh, vh, nullptr, 1);

    cudaFuncSetAttribute(flash_h_kernel,
                         cudaFuncAttributeMaxDynamicSharedMemorySize, FLASH_SMEM);
    flash_h_kernel<<<dim3(SS / 128, BB * HH), 256, FLASH_SMEM>>>(qh, kh, vh, ah);

    // output projection (float output)
    gemm_h_kernel<<<dim3(DD / 128, MM / 128), 128, GEMM_SMEM>>>(
        ah, who, bo, bo, bo, ropep, nullptr, nullptr, nullptr, out, 0);
}